// round 1
// baseline (speedup 1.0000x reference)
#include <cuda_runtime.h>
#include <math.h>

// ---------------- problem constants ----------------
#define NB      16
#define T2N     8
#define BT      128            // NB * T2N
#define HWN     196
#define ROWS    25088          // BT * HWN
#define CC      768
#define NHEAD   12
#define HD      64
#define SCALE_A 0.125f         // 1/sqrt(64)
#define TOKENS  3136

// ---------------- scratch (device globals; no allocs allowed) ----------------
__device__ float g_xa [25088u*768u];   // x_a (even slices), fp32
__device__ float g_xd [25088u*768u];   // x_d (odd slices)
__device__ float g_xdn[25088u*768u];   // x_d_new, later reused as G2
__device__ float g_q  [25088u*768u];   // Q projection
__device__ float g_kv [25088u*1536u];  // KV projection
__device__ float g_o  [25088u*768u];   // attention output
__device__ float g_mxa[25088u];        // mean_c x_a orig
__device__ float g_mxd[25088u];        // mean_c x_d orig
__device__ float g_mg2[25088u];        // mean_c gelu (stage a)

__device__ __forceinline__ float gelu_f(float x) {
    return 0.5f * x * (1.0f + erff(x * 0.70710678118654752f));
}

// ---------------- gather: x_in -> x_a, x_d (+ row means) ----------------
// x[b, nt*4+t, nh, nw, c] = x_in[b, nt*784 + s*4 + t, c],  s = nh*14+nw
__global__ void gather_kernel(const float* __restrict__ x_in,
                              float* __restrict__ xa, float* __restrict__ xd,
                              float* __restrict__ mxa, float* __restrict__ mxd)
{
    int row = blockIdx.x;              // bt*196 + s
    int bt  = row / HWN, s = row % HWN;
    int b   = bt >> 3,  t2 = bt & 7;
    int tt  = t2 * 2;                  // even slice
    int nt_a = tt >> 2,     t_a = tt & 3;
    int nt_d = (tt+1) >> 2, t_d = (tt+1) & 3;
    size_t base_a = ((size_t)b*TOKENS + (size_t)nt_a*784 + s*4 + t_a) * CC;
    size_t base_d = ((size_t)b*TOKENS + (size_t)nt_d*784 + s*4 + t_d) * CC;

    float suma = 0.f, sumd = 0.f;
    int c4 = threadIdx.x * 4;
    if (c4 < CC) {
        float4 va = *(const float4*)&x_in[base_a + c4];
        float4 vd = *(const float4*)&x_in[base_d + c4];
        *(float4*)&xa[(size_t)row*CC + c4] = va;
        *(float4*)&xd[(size_t)row*CC + c4] = vd;
        suma = va.x+va.y+va.z+va.w;
        sumd = vd.x+vd.y+vd.z+vd.w;
    }
    __shared__ float ra[256], rd[256];
    ra[threadIdx.x] = suma; rd[threadIdx.x] = sumd;
    __syncthreads();
    for (int st = 128; st > 0; st >>= 1) {
        if (threadIdx.x < st) {
            ra[threadIdx.x] += ra[threadIdx.x + st];
            rd[threadIdx.x] += rd[threadIdx.x + st];
        }
        __syncthreads();
    }
    if (threadIdx.x == 0) {
        mxa[row] = ra[0] * (1.f/768.f);
        mxd[row] = rd[0] * (1.f/768.f);
    }
}

// ---------------- generic tiled SGEMM: Y = epi(A @ W + bias) ----------------
// A: MxK row-major, W: KxN row-major. 64x64 tile, BK=16, 256 thr, 4x4 microtile.
// M%64==0, N%64==0, K%16==0 guaranteed by problem shapes.
#define GBM 64
#define GBN 64
#define GBK 16
#define EPI_BIAS     0
#define EPI_GELU     1
#define EPI_GELU_SUB 2   // Y = Xsub - gelu(A@W + b)

__global__ __launch_bounds__(256) void gemm_kernel(
    const float* __restrict__ A, const float* __restrict__ W,
    const float* __restrict__ bias, float* __restrict__ Y,
    const float* __restrict__ Xsub, int M, int N, int K, int epi)
{
    __shared__ float As[GBK][GBM + 4];
    __shared__ float Bs[GBK][GBN];
    const int tid = threadIdx.x;
    const int bm = blockIdx.y * GBM;
    const int bn = blockIdx.x * GBN;

    const int a_row = tid >> 2;            // 0..63
    const int a_col = (tid & 3) << 2;      // 0,4,8,12
    const int b_row = tid >> 4;            // 0..15
    const int b_col = (tid & 15) << 2;     // 0..60
    const int tr = (tid >> 4) << 2;        // 0..60
    const int tc = (tid & 15) << 2;        // 0..60

    float acc[4][4] = {};
    const float* Aptr = A + (size_t)(bm + a_row) * K + a_col;
    const float* Wptr = W + (size_t)b_row * N + bn + b_col;

    for (int k0 = 0; k0 < K; k0 += GBK) {
        float4 av = *(const float4*)(Aptr + k0);
        As[a_col+0][a_row] = av.x;
        As[a_col+1][a_row] = av.y;
        As[a_col+2][a_row] = av.z;
        As[a_col+3][a_row] = av.w;
        float4 bv = *(const float4*)(Wptr + (size_t)k0 * N);
        *(float4*)&Bs[b_row][b_col] = bv;
        __syncthreads();
        #pragma unroll
        for (int kk = 0; kk < GBK; kk++) {
            float a0[4], b0[4];
            *(float4*)a0 = *(const float4*)&As[kk][tr];
            *(float4*)b0 = *(const float4*)&Bs[kk][tc];
            #pragma unroll
            for (int i = 0; i < 4; i++)
                #pragma unroll
                for (int j = 0; j < 4; j++)
                    acc[i][j] = fmaf(a0[i], b0[j], acc[i][j]);
        }
        __syncthreads();
    }

    float4 bvec = *(const float4*)&bias[bn + tc];
    float bb[4] = {bvec.x, bvec.y, bvec.z, bvec.w};
    #pragma unroll
    for (int i = 0; i < 4; i++) {
        int row = bm + tr + i;
        float v[4];
        #pragma unroll
        for (int j = 0; j < 4; j++) v[j] = acc[i][j] + bb[j];
        float4 r;
        if (epi == EPI_BIAS) {
            r.x = v[0]; r.y = v[1]; r.z = v[2]; r.w = v[3];
        } else if (epi == EPI_GELU) {
            r.x = gelu_f(v[0]); r.y = gelu_f(v[1]); r.z = gelu_f(v[2]); r.w = gelu_f(v[3]);
        } else { // GELU_SUB
            float4 xs = *(const float4*)&Xsub[(size_t)row * N + bn + tc];
            r.x = xs.x - gelu_f(v[0]); r.y = xs.y - gelu_f(v[1]);
            r.z = xs.z - gelu_f(v[2]); r.w = xs.w - gelu_f(v[3]);
        }
        *(float4*)&Y[(size_t)row * N + bn + tc] = r;
    }
}

// ---------------- attention: per (bt, head), 196 q x 196 k, 2-pass ----------
#define ATTN_SMEM (2 * 196 * 64 * 4)   // K + V fp32 = 100352 B

__global__ __launch_bounds__(256, 1) void attn_kernel(
    const float* __restrict__ Q, const float* __restrict__ KV, float* __restrict__ O)
{
    extern __shared__ float sm[];
    float* Ks = sm;
    float* Vs = sm + HWN * HD;
    int bt = blockIdx.x / NHEAD;
    int h  = blockIdx.x % NHEAD;

    const float* kvbase = KV + (size_t)bt * HWN * 1536 + h * HD;
    for (int idx = threadIdx.x; idx < HWN * 16; idx += blockDim.x) {
        int r = idx >> 4, c4 = (idx & 15) << 2;
        *(float4*)&Ks[r*HD + c4] = *(const float4*)&kvbase[(size_t)r*1536 + c4];
        *(float4*)&Vs[r*HD + c4] = *(const float4*)&kvbase[(size_t)r*1536 + 768 + c4];
    }
    __syncthreads();

    int t = threadIdx.x;
    if (t >= HWN) return;

    float q[HD];
    const float* qp = Q + ((size_t)bt * HWN + t) * CC + h * HD;
    #pragma unroll
    for (int d4 = 0; d4 < HD; d4 += 4)
        *(float4*)&q[d4] = *(const float4*)&qp[d4];

    // pass 1: online max & sum-exp
    float m = -1e30f, l = 0.f;
    for (int j = 0; j < HWN; j++) {
        const float* kr = &Ks[j * HD];
        float s0 = 0.f, s1 = 0.f, s2 = 0.f, s3 = 0.f;
        #pragma unroll
        for (int d4 = 0; d4 < HD; d4 += 16) {
            float4 k0 = *(const float4*)&kr[d4 + 0];
            float4 k1 = *(const float4*)&kr[d4 + 4];
            float4 k2 = *(const float4*)&kr[d4 + 8];
            float4 k3 = *(const float4*)&kr[d4 + 12];
            s0 = fmaf(q[d4+0],k0.x,s0); s0 = fmaf(q[d4+1],k0.y,s0); s0 = fmaf(q[d4+2],k0.z,s0); s0 = fmaf(q[d4+3],k0.w,s0);
            s1 = fmaf(q[d4+4],k1.x,s1); s1 = fmaf(q[d4+5],k1.y,s1); s1 = fmaf(q[d4+6],k1.z,s1); s1 = fmaf(q[d4+7],k1.w,s1);
            s2 = fmaf(q[d4+8],k2.x,s2); s2 = fmaf(q[d4+9],k2.y,s2); s2 = fmaf(q[d4+10],k2.z,s2); s2 = fmaf(q[d4+11],k2.w,s2);
            s3 = fmaf(q[d4+12],k3.x,s3); s3 = fmaf(q[d4+13],k3.y,s3); s3 = fmaf(q[d4+14],k3.z,s3); s3 = fmaf(q[d4+15],k3.w,s3);
        }
        float s = ((s0+s1)+(s2+s3)) * SCALE_A;
        if (s > m) { l = l * __expf(m - s) + 1.f; m = s; }
        else       { l += __expf(s - m); }
    }
    float inv_l = 1.f / l;

    // pass 2: recompute scores, accumulate output
    float o[HD];
    #pragma unroll
    for (int d = 0; d < HD; d++) o[d] = 0.f;
    for (int j = 0; j < HWN; j++) {
        const float* kr = &Ks[j * HD];
        float s0 = 0.f, s1 = 0.f, s2 = 0.f, s3 = 0.f;
        #pragma unroll
        for (int d4 = 0; d4 < HD; d4 += 16) {
            float4 k0 = *(const float4*)&kr[d4 + 0];
            float4 k1 = *(const float4*)&kr[d4 + 4];
            float4 k2 = *(const float4*)&kr[d4 + 8];
            float4 k3 = *(const float4*)&kr[d4 + 12];
            s0 = fmaf(q[d4+0],k0.x,s0); s0 = fmaf(q[d4+1],k0.y,s0); s0 = fmaf(q[d4+2],k0.z,s0); s0 = fmaf(q[d4+3],k0.w,s0);
            s1 = fmaf(q[d4+4],k1.x,s1); s1 = fmaf(q[d4+5],k1.y,s1); s1 = fmaf(q[d4+6],k1.z,s1); s1 = fmaf(q[d4+7],k1.w,s1);
            s2 = fmaf(q[d4+8],k2.x,s2); s2 = fmaf(q[d4+9],k2.y,s2); s2 = fmaf(q[d4+10],k2.z,s2); s2 = fmaf(q[d4+11],k2.w,s2);
            s3 = fmaf(q[d4+12],k3.x,s3); s3 = fmaf(q[d4+13],k3.y,s3); s3 = fmaf(q[d4+14],k3.z,s3); s3 = fmaf(q[d4+15],k3.w,s3);
        }
        float p = __expf(((s0+s1)+(s2+s3)) * SCALE_A - m);
        const float* vr = &Vs[j * HD];
        #pragma unroll
        for (int d4 = 0; d4 < HD; d4 += 4) {
            float4 v4 = *(const float4*)&vr[d4];
            o[d4+0] = fmaf(p, v4.x, o[d4+0]);
            o[d4+1] = fmaf(p, v4.y, o[d4+1]);
            o[d4+2] = fmaf(p, v4.z, o[d4+2]);
            o[d4+3] = fmaf(p, v4.w, o[d4+3]);
        }
    }
    float* op = O + ((size_t)bt * HWN + t) * CC + h * HD;
    #pragma unroll
    for (int d4 = 0; d4 < HD; d4 += 4) {
        float4 r;
        r.x = o[d4+0] * inv_l; r.y = o[d4+1] * inv_l;
        r.z = o[d4+2] * inv_l; r.w = o[d4+3] * inv_l;
        *(float4*)&op[d4] = r;
    }
}

// ---------------- row mean over C=768 (one warp per row) --------------------
__global__ void rowmean_kernel(const float* __restrict__ X, float* __restrict__ out)
{
    int warp = threadIdx.x >> 5;
    int lane = threadIdx.x & 31;
    int row = blockIdx.x * 8 + warp;
    const float* p = X + (size_t)row * CC;
    float s = 0.f;
    #pragma unroll
    for (int k = 0; k < 6; k++) {
        float4 v = *(const float4*)&p[lane*4 + k*128];
        s += v.x + v.y + v.z + v.w;
    }
    #pragma unroll
    for (int off = 16; off; off >>= 1) s += __shfl_xor_sync(0xffffffffu, s, off);
    if (lane == 0) out[row] = s * (1.0f/768.0f);
}

// ---------------- final: pool_a assembly ------------------------------------
__global__ void final_kernel(const float* __restrict__ mxa, const float* __restrict__ mxd,
                             const float* __restrict__ mg2, float* __restrict__ out)
{
    int i = blockIdx.x * blockDim.x + threadIdx.x;
    if (i < ROWS) out[i] = 0.5f * (mxd[i] - mxa[i]) - mg2[i];
}

// ---------------- launch ----------------------------------------------------
extern "C" void kernel_launch(void* const* d_in, const int* in_sizes, int n_in,
                              void* d_out, int out_size)
{
    const float* x_in  = (const float*)d_in[0];
    const float* Wq_d  = (const float*)d_in[1];
    const float* bq_d  = (const float*)d_in[2];
    const float* Wkv_a = (const float*)d_in[3];
    const float* bkv_a = (const float*)d_in[4];
    const float* Wq_a  = (const float*)d_in[5];
    const float* bq_a  = (const float*)d_in[6];
    const float* Wkv_d = (const float*)d_in[7];
    const float* bkv_d = (const float*)d_in[8];
    const float* Wp_d  = (const float*)d_in[9];
    const float* bp_d  = (const float*)d_in[10];
    const float* Wp_a  = (const float*)d_in[11];
    const float* bp_a  = (const float*)d_in[12];
    float* out = (float*)d_out;

    float *xa, *xd, *xdn, *q, *kv, *o, *mxa, *mxd, *mg2;
    cudaGetSymbolAddress((void**)&xa,  g_xa);
    cudaGetSymbolAddress((void**)&xd,  g_xd);
    cudaGetSymbolAddress((void**)&xdn, g_xdn);
    cudaGetSymbolAddress((void**)&q,   g_q);
    cudaGetSymbolAddress((void**)&kv,  g_kv);
    cudaGetSymbolAddress((void**)&o,   g_o);
    cudaGetSymbolAddress((void**)&mxa, g_mxa);
    cudaGetSymbolAddress((void**)&mxd, g_mxd);
    cudaGetSymbolAddress((void**)&mg2, g_mg2);

    cudaFuncSetAttribute(attn_kernel, cudaFuncAttributeMaxDynamicSharedMemorySize, ATTN_SMEM);

    dim3 g768(12, 392), g1536(24, 392);

    // gather + original means
    gather_kernel<<<ROWS, 256>>>(x_in, xa, xd, mxa, mxd);

    // ---- stage d: q from x_d, kv from x_a ----
    gemm_kernel<<<g768,  256>>>(xd, Wq_d,  bq_d,  q,  nullptr, ROWS, 768,  768, EPI_BIAS);
    gemm_kernel<<<g1536, 256>>>(xa, Wkv_a, bkv_a, kv, nullptr, ROWS, 1536, 768, EPI_BIAS);
    attn_kernel<<<BT * NHEAD, 256, ATTN_SMEM>>>(q, kv, o);
    // x_d_new = x_d - gelu(O @ Wp_d + bp_d)
    gemm_kernel<<<g768, 256>>>(o, Wp_d, bp_d, xdn, xd, ROWS, 768, 768, EPI_GELU_SUB);
    // x_d_out = mean_c(x_d_new)  -> second half of output
    rowmean_kernel<<<ROWS/8, 256>>>(xdn, out + ROWS);

    // ---- stage a: q from x_a, kv from x_d_new ----
    gemm_kernel<<<g768,  256>>>(xa,  Wq_a,  bq_a,  q,  nullptr, ROWS, 768,  768, EPI_BIAS);
    gemm_kernel<<<g1536, 256>>>(xdn, Wkv_d, bkv_d, kv, nullptr, ROWS, 1536, 768, EPI_BIAS);
    attn_kernel<<<BT * NHEAD, 256, ATTN_SMEM>>>(q, kv, o);
    // G2 = gelu(O @ Wp_a + bp_a)  (reuse xdn buffer)
    gemm_kernel<<<g768, 256>>>(o, Wp_a, bp_a, xdn, nullptr, ROWS, 768, 768, EPI_GELU);
    rowmean_kernel<<<ROWS/8, 256>>>(xdn, mg2);

    // pool_a = 0.5*(mean x_d0 - mean x_a0) - mean G2
    final_kernel<<<(ROWS + 255)/256, 256>>>(mxa, mxd, mg2, out);
}

// round 3
// speedup vs baseline: 2.1617x; 2.1617x over previous
#include <cuda_runtime.h>
#include <math.h>
#include <stdint.h>

// ---------------- problem constants ----------------
#define NB      16
#define T2N     8
#define BT      128            // NB * T2N
#define HWN     196
#define ROWS    25088          // BT * HWN
#define CC      768
#define NHEAD   12
#define HD      64
#define SCALE_A 0.125f         // 1/sqrt(64)
#define TOKENS  3136

// ---------------- scratch (device globals; no allocs allowed) ----------------
__device__ float g_xa [25088u*768u];
__device__ float g_xd [25088u*768u];
__device__ float g_xdn[25088u*768u];
__device__ float g_q  [25088u*768u];
__device__ float g_kv [25088u*1536u];
__device__ float g_o  [25088u*768u];
__device__ float g_mxa[25088u];
__device__ float g_mxd[25088u];
__device__ float g_mg2[25088u];

__device__ __forceinline__ float gelu_f(float x) {
    return 0.5f * x * (1.0f + erff(x * 0.70710678118654752f));
}

__device__ __forceinline__ float tf32_rnd(float x) {
    uint32_t u;
    asm("cvt.rna.tf32.f32 %0, %1;" : "=r"(u) : "f"(x));
    return __uint_as_float(u);
}

// ---------------- gather: x_in -> x_a, x_d (+ row means) ----------------
__global__ void gather_kernel(const float* __restrict__ x_in,
                              float* __restrict__ xa, float* __restrict__ xd,
                              float* __restrict__ mxa, float* __restrict__ mxd)
{
    int row = blockIdx.x;              // bt*196 + s
    int bt  = row / HWN, s = row % HWN;
    int b   = bt >> 3,  t2 = bt & 7;
    int tt  = t2 * 2;
    int nt_a = tt >> 2,     t_a = tt & 3;
    int nt_d = (tt+1) >> 2, t_d = (tt+1) & 3;
    size_t base_a = ((size_t)b*TOKENS + (size_t)nt_a*784 + s*4 + t_a) * CC;
    size_t base_d = ((size_t)b*TOKENS + (size_t)nt_d*784 + s*4 + t_d) * CC;

    float suma = 0.f, sumd = 0.f;
    int c4 = threadIdx.x * 4;
    if (c4 < CC) {
        float4 va = *(const float4*)&x_in[base_a + c4];
        float4 vd = *(const float4*)&x_in[base_d + c4];
        *(float4*)&xa[(size_t)row*CC + c4] = va;
        *(float4*)&xd[(size_t)row*CC + c4] = vd;
        suma = va.x+va.y+va.z+va.w;
        sumd = vd.x+vd.y+vd.z+vd.w;
    }
    __shared__ float ra[256], rd[256];
    ra[threadIdx.x] = suma; rd[threadIdx.x] = sumd;
    __syncthreads();
    for (int st = 128; st > 0; st >>= 1) {
        if (threadIdx.x < st) {
            ra[threadIdx.x] += ra[threadIdx.x + st];
            rd[threadIdx.x] += rd[threadIdx.x + st];
        }
        __syncthreads();
    }
    if (threadIdx.x == 0) {
        mxa[row] = ra[0] * (1.f/768.f);
        mxd[row] = rd[0] * (1.f/768.f);
    }
}

// ---------------- tf32 tensor-core GEMM: Y = epi(A @ W + bias) --------------
// A: MxK row-major fp32, W: KxN row-major fp32. Block 128x128x16, 8 warps,
// warp tile 64x32 via mma.sync.m16n8k8.tf32. Double-buffered smem, tf32
// rounding applied at smem store. M%128==0, N%128==0, K%16==0.
#define TBM 128
#define TBN 128
#define TBK 16
#define TP  136    // smem row pitch; 136 mod 32 == 8 -> conflict-free frag loads

#define EPI_BIAS     0
#define EPI_GELU     1
#define EPI_GELU_SUB 2

__global__ __launch_bounds__(256, 2) void gemm_tc(
    const float* __restrict__ A, const float* __restrict__ W,
    const float* __restrict__ bias, float* __restrict__ Y,
    const float* __restrict__ Xsub, int M, int N, int K, int epi)
{
    __shared__ float As[2][TBK][TP];   // [k][m]
    __shared__ float Bs[2][TBK][TP];   // [k][n]

    const int tid  = threadIdx.x;
    const int bm   = blockIdx.y * TBM;
    const int bn   = blockIdx.x * TBN;
    const int lane = tid & 31, warp = tid >> 5;
    const int wm   = (warp & 1) * 64;
    const int wn   = (warp >> 1) * 32;
    const int g    = lane >> 2;     // 0..7
    const int qp   = lane & 3;      // 0..3

    // global load mapping
    const int ar = tid >> 1;            // 0..127
    const int ac = (tid & 1) * 8;       // 0 or 8
    const int br = tid >> 4;            // 0..15
    const int bc = (tid & 15) * 8;      // 0..120

    const float* Ag = A + (size_t)(bm + ar) * K + ac;
    const float* Wg = W + (size_t)br * N + bn + bc;

    float acc[4][4][4];
    #pragma unroll
    for (int i=0;i<4;i++)
        #pragma unroll
        for (int j=0;j<4;j++)
            #pragma unroll
            for (int r=0;r<4;r++) acc[i][j][r]=0.f;

    // prologue: load tile 0
    {
        float4 a0 = *(const float4*)(Ag);
        float4 a1 = *(const float4*)(Ag + 4);
        As[0][ac+0][ar]=tf32_rnd(a0.x); As[0][ac+1][ar]=tf32_rnd(a0.y);
        As[0][ac+2][ar]=tf32_rnd(a0.z); As[0][ac+3][ar]=tf32_rnd(a0.w);
        As[0][ac+4][ar]=tf32_rnd(a1.x); As[0][ac+5][ar]=tf32_rnd(a1.y);
        As[0][ac+6][ar]=tf32_rnd(a1.z); As[0][ac+7][ar]=tf32_rnd(a1.w);
        float4 b0 = *(const float4*)(Wg);
        float4 b1 = *(const float4*)(Wg + 4);
        Bs[0][br][bc+0]=tf32_rnd(b0.x); Bs[0][br][bc+1]=tf32_rnd(b0.y);
        Bs[0][br][bc+2]=tf32_rnd(b0.z); Bs[0][br][bc+3]=tf32_rnd(b0.w);
        Bs[0][br][bc+4]=tf32_rnd(b1.x); Bs[0][br][bc+5]=tf32_rnd(b1.y);
        Bs[0][br][bc+6]=tf32_rnd(b1.z); Bs[0][br][bc+7]=tf32_rnd(b1.w);
    }
    __syncthreads();

    const int nk = K / TBK;
    for (int kt = 0; kt < nk; kt++) {
        const int cur = kt & 1;
        float4 na0, na1, nb0, nb1;
        const bool has_next = (kt + 1 < nk);
        if (has_next) {
            const float* Ag2 = Ag + (kt+1)*TBK;
            na0 = *(const float4*)(Ag2);
            na1 = *(const float4*)(Ag2 + 4);
            const float* Wg2 = Wg + (size_t)(kt+1)*TBK * N;
            nb0 = *(const float4*)(Wg2);
            nb1 = *(const float4*)(Wg2 + 4);
        }
        #pragma unroll
        for (int ks = 0; ks < 2; ks++) {
            const int kk = ks * 8;
            uint32_t af[4][4], bf[4][2];
            #pragma unroll
            for (int mi=0; mi<4; mi++) {
                int rb = wm + mi*16;
                af[mi][0] = __float_as_uint(As[cur][kk+qp  ][rb+g  ]);
                af[mi][1] = __float_as_uint(As[cur][kk+qp  ][rb+g+8]);
                af[mi][2] = __float_as_uint(As[cur][kk+qp+4][rb+g  ]);
                af[mi][3] = __float_as_uint(As[cur][kk+qp+4][rb+g+8]);
            }
            #pragma unroll
            for (int ni=0; ni<4; ni++) {
                int cb = wn + ni*8;
                bf[ni][0] = __float_as_uint(Bs[cur][kk+qp  ][cb+g]);
                bf[ni][1] = __float_as_uint(Bs[cur][kk+qp+4][cb+g]);
            }
            #pragma unroll
            for (int mi=0; mi<4; mi++)
                #pragma unroll
                for (int ni=0; ni<4; ni++)
                    asm volatile(
                        "mma.sync.aligned.m16n8k8.row.col.f32.tf32.tf32.f32 "
                        "{%0,%1,%2,%3}, {%4,%5,%6,%7}, {%8,%9}, {%0,%1,%2,%3};\n"
                        : "+f"(acc[mi][ni][0]), "+f"(acc[mi][ni][1]),
                          "+f"(acc[mi][ni][2]), "+f"(acc[mi][ni][3])
                        : "r"(af[mi][0]), "r"(af[mi][1]),
                          "r"(af[mi][2]), "r"(af[mi][3]),
                          "r"(bf[ni][0]), "r"(bf[ni][1]));
        }
        if (has_next) {
            const int nxt = cur ^ 1;
            As[nxt][ac+0][ar]=tf32_rnd(na0.x); As[nxt][ac+1][ar]=tf32_rnd(na0.y);
            As[nxt][ac+2][ar]=tf32_rnd(na0.z); As[nxt][ac+3][ar]=tf32_rnd(na0.w);
            As[nxt][ac+4][ar]=tf32_rnd(na1.x); As[nxt][ac+5][ar]=tf32_rnd(na1.y);
            As[nxt][ac+6][ar]=tf32_rnd(na1.z); As[nxt][ac+7][ar]=tf32_rnd(na1.w);
            Bs[nxt][br][bc+0]=tf32_rnd(nb0.x); Bs[nxt][br][bc+1]=tf32_rnd(nb0.y);
            Bs[nxt][br][bc+2]=tf32_rnd(nb0.z); Bs[nxt][br][bc+3]=tf32_rnd(nb0.w);
            Bs[nxt][br][bc+4]=tf32_rnd(nb1.x); Bs[nxt][br][bc+5]=tf32_rnd(nb1.y);
            Bs[nxt][br][bc+6]=tf32_rnd(nb1.z); Bs[nxt][br][bc+7]=tf32_rnd(nb1.w);
        }
        __syncthreads();
    }

    // epilogue
    #pragma unroll
    for (int mi=0; mi<4; mi++) {
        const int r0 = bm + wm + mi*16 + g;
        const int r1 = r0 + 8;
        #pragma unroll
        for (int ni=0; ni<4; ni++) {
            const int c = bn + wn + ni*8 + qp*2;
            const float b0v = __ldg(&bias[c]);
            const float b1v = __ldg(&bias[c+1]);
            float v00 = acc[mi][ni][0] + b0v, v01 = acc[mi][ni][1] + b1v;
            float v10 = acc[mi][ni][2] + b0v, v11 = acc[mi][ni][3] + b1v;
            float2 o0, o1;
            if (epi == EPI_BIAS) {
                o0 = make_float2(v00, v01);
                o1 = make_float2(v10, v11);
            } else if (epi == EPI_GELU) {
                o0 = make_float2(gelu_f(v00), gelu_f(v01));
                o1 = make_float2(gelu_f(v10), gelu_f(v11));
            } else {
                float2 x0 = *(const float2*)&Xsub[(size_t)r0*N + c];
                float2 x1 = *(const float2*)&Xsub[(size_t)r1*N + c];
                o0 = make_float2(x0.x - gelu_f(v00), x0.y - gelu_f(v01));
                o1 = make_float2(x1.x - gelu_f(v10), x1.y - gelu_f(v11));
            }
            *(float2*)&Y[(size_t)r0*N + c] = o0;
            *(float2*)&Y[(size_t)r1*N + c] = o1;
        }
    }
}

// ---------------- attention: per (bt, head), single-pass flash --------------
#define ATTN_SMEM (2 * 196 * 64 * 4)   // K + V fp32 = 100352 B

__global__ __launch_bounds__(256, 1) void attn_kernel(
    const float* __restrict__ Q, const float* __restrict__ KV, float* __restrict__ O)
{
    extern __shared__ float sm[];
    float* Ks = sm;
    float* Vs = sm + HWN * HD;
    int bt = blockIdx.x / NHEAD;
    int h  = blockIdx.x % NHEAD;

    const float* kvbase = KV + (size_t)bt * HWN * 1536 + h * HD;
    for (int idx = threadIdx.x; idx < HWN * 16; idx += blockDim.x) {
        int r = idx >> 4, c4 = (idx & 15) << 2;
        *(float4*)&Ks[r*HD + c4] = *(const float4*)&kvbase[(size_t)r*1536 + c4];
        *(float4*)&Vs[r*HD + c4] = *(const float4*)&kvbase[(size_t)r*1536 + 768 + c4];
    }
    __syncthreads();

    int t = threadIdx.x;
    if (t >= HWN) return;

    float q[HD];
    const float* qp = Q + ((size_t)bt * HWN + t) * CC + h * HD;
    #pragma unroll
    for (int d4 = 0; d4 < HD; d4 += 4)
        *(float4*)&q[d4] = *(const float4*)&qp[d4];

    float m = -1e30f, l = 0.f;
    float o[HD];
    #pragma unroll
    for (int d = 0; d < HD; d++) o[d] = 0.f;

    for (int j = 0; j < HWN; j++) {
        const float* kr = &Ks[j * HD];
        float s0 = 0.f, s1 = 0.f, s2 = 0.f, s3 = 0.f;
        #pragma unroll
        for (int d4 = 0; d4 < HD; d4 += 16) {
            float4 k0 = *(const float4*)&kr[d4 + 0];
            float4 k1 = *(const float4*)&kr[d4 + 4];
            float4 k2 = *(const float4*)&kr[d4 + 8];
            float4 k3 = *(const float4*)&kr[d4 + 12];
            s0 = fmaf(q[d4+0],k0.x,s0); s0 = fmaf(q[d4+1],k0.y,s0); s0 = fmaf(q[d4+2],k0.z,s0); s0 = fmaf(q[d4+3],k0.w,s0);
            s1 = fmaf(q[d4+4],k1.x,s1); s1 = fmaf(q[d4+5],k1.y,s1); s1 = fmaf(q[d4+6],k1.z,s1); s1 = fmaf(q[d4+7],k1.w,s1);
            s2 = fmaf(q[d4+8],k2.x,s2); s2 = fmaf(q[d4+9],k2.y,s2); s2 = fmaf(q[d4+10],k2.z,s2); s2 = fmaf(q[d4+11],k2.w,s2);
            s3 = fmaf(q[d4+12],k3.x,s3); s3 = fmaf(q[d4+13],k3.y,s3); s3 = fmaf(q[d4+14],k3.z,s3); s3 = fmaf(q[d4+15],k3.w,s3);
        }
        float s = ((s0+s1)+(s2+s3)) * SCALE_A;
        float p;
        if (s > m) {
            float corr = __expf(m - s);
            l = fmaf(l, corr, 1.f);
            #pragma unroll
            for (int d = 0; d < HD; d++) o[d] *= corr;
            m = s;
            p = 1.f;
        } else {
            p = __expf(s - m);
            l += p;
        }
        const float* vr = &Vs[j * HD];
        #pragma unroll
        for (int d4 = 0; d4 < HD; d4 += 4) {
            float4 v4 = *(const float4*)&vr[d4];
            o[d4+0] = fmaf(p, v4.x, o[d4+0]);
            o[d4+1] = fmaf(p, v4.y, o[d4+1]);
            o[d4+2] = fmaf(p, v4.z, o[d4+2]);
            o[d4+3] = fmaf(p, v4.w, o[d4+3]);
        }
    }
    float inv_l = 1.f / l;
    float* op = O + ((size_t)bt * HWN + t) * CC + h * HD;
    #pragma unroll
    for (int d4 = 0; d4 < HD; d4 += 4) {
        float4 r;
        r.x = o[d4+0] * inv_l; r.y = o[d4+1] * inv_l;
        r.z = o[d4+2] * inv_l; r.w = o[d4+3] * inv_l;
        *(float4*)&op[d4] = r;
    }
}

// ---------------- row mean over C=768 (one warp per row) --------------------
__global__ void rowmean_kernel(const float* __restrict__ X, float* __restrict__ out)
{
    int warp = threadIdx.x >> 5;
    int lane = threadIdx.x & 31;
    int row = blockIdx.x * 8 + warp;
    const float* p = X + (size_t)row * CC;
    float s = 0.f;
    #pragma unroll
    for (int k = 0; k < 6; k++) {
        float4 v = *(const float4*)&p[lane*4 + k*128];
        s += v.x + v.y + v.z + v.w;
    }
    #pragma unroll
    for (int off = 16; off; off >>= 1) s += __shfl_xor_sync(0xffffffffu, s, off);
    if (lane == 0) out[row] = s * (1.0f/768.0f);
}

// ---------------- final: pool_a assembly ------------------------------------
__global__ void final_kernel(const float* __restrict__ mxa, const float* __restrict__ mxd,
                             const float* __restrict__ mg2, float* __restrict__ out)
{
    int i = blockIdx.x * blockDim.x + threadIdx.x;
    if (i < ROWS) out[i] = 0.5f * (mxd[i] - mxa[i]) - mg2[i];
}

// ---------------- launch ----------------------------------------------------
extern "C" void kernel_launch(void* const* d_in, const int* in_sizes, int n_in,
                              void* d_out, int out_size)
{
    const float* x_in  = (const float*)d_in[0];
    const float* Wq_d  = (const float*)d_in[1];
    const float* bq_d  = (const float*)d_in[2];
    const float* Wkv_a = (const float*)d_in[3];
    const float* bkv_a = (const float*)d_in[4];
    const float* Wq_a  = (const float*)d_in[5];
    const float* bq_a  = (const float*)d_in[6];
    const float* Wkv_d = (const float*)d_in[7];
    const float* bkv_d = (const float*)d_in[8];
    const float* Wp_d  = (const float*)d_in[9];
    const float* bp_d  = (const float*)d_in[10];
    const float* Wp_a  = (const float*)d_in[11];
    const float* bp_a  = (const float*)d_in[12];
    float* out = (float*)d_out;

    float *xa, *xd, *xdn, *q, *kv, *o, *mxa, *mxd, *mg2;
    cudaGetSymbolAddress((void**)&xa,  g_xa);
    cudaGetSymbolAddress((void**)&xd,  g_xd);
    cudaGetSymbolAddress((void**)&xdn, g_xdn);
    cudaGetSymbolAddress((void**)&q,   g_q);
    cudaGetSymbolAddress((void**)&kv,  g_kv);
    cudaGetSymbolAddress((void**)&o,   g_o);
    cudaGetSymbolAddress((void**)&mxa, g_mxa);
    cudaGetSymbolAddress((void**)&mxd, g_mxd);
    cudaGetSymbolAddress((void**)&mg2, g_mg2);

    cudaFuncSetAttribute(attn_kernel, cudaFuncAttributeMaxDynamicSharedMemorySize, ATTN_SMEM);

    dim3 g768(6, 196), g1536(12, 196);

    gather_kernel<<<ROWS, 256>>>(x_in, xa, xd, mxa, mxd);

    // ---- stage d: q from x_d, kv from x_a ----
    gemm_tc<<<g768,  256>>>(xd, Wq_d,  bq_d,  q,  nullptr, ROWS, 768,  768, EPI_BIAS);
    gemm_tc<<<g1536, 256>>>(xa, Wkv_a, bkv_a, kv, nullptr, ROWS, 1536, 768, EPI_BIAS);
    attn_kernel<<<BT * NHEAD, 256, ATTN_SMEM>>>(q, kv, o);
    gemm_tc<<<g768, 256>>>(o, Wp_d, bp_d, xdn, xd, ROWS, 768, 768, EPI_GELU_SUB);
    rowmean_kernel<<<ROWS/8, 256>>>(xdn, out + ROWS);

    // ---- stage a: q from x_a, kv from x_d_new ----
    gemm_tc<<<g768,  256>>>(xa,  Wq_a,  bq_a,  q,  nullptr, ROWS, 768,  768, EPI_BIAS);
    gemm_tc<<<g1536, 256>>>(xdn, Wkv_d, bkv_d, kv, nullptr, ROWS, 1536, 768, EPI_BIAS);
    attn_kernel<<<BT * NHEAD, 256, ATTN_SMEM>>>(q, kv, o);
    gemm_tc<<<g768, 256>>>(o, Wp_a, bp_a, xdn, nullptr, ROWS, 768, 768, EPI_GELU);
    rowmean_kernel<<<ROWS/8, 256>>>(xdn, mg2);

    final_kernel<<<(ROWS + 255)/256, 256>>>(mxa, mxd, mg2, out);
}

// round 4
// speedup vs baseline: 3.0008x; 1.3882x over previous
#include <cuda_runtime.h>
#include <math.h>
#include <stdint.h>

// ---------------- problem constants ----------------
#define NB      16
#define T2N     8
#define BT      128            // NB * T2N
#define HWN     196
#define ROWS    25088          // BT * HWN
#define CC      768
#define NHEAD   12
#define HD      64
#define SCALE_A 0.125f         // 1/sqrt(64)
#define TOKENS  3136

// ---------------- scratch (device globals; no allocs allowed) ----------------
__device__ float g_xa [25088u*768u];
__device__ float g_xd [25088u*768u];
__device__ float g_xdn[25088u*768u];
__device__ float g_q  [25088u*768u];
__device__ float g_kv [25088u*1536u];
__device__ float g_o  [25088u*768u];
__device__ float g_mxa[25088u];
__device__ float g_mxd[25088u];
__device__ float g_mg2[25088u];

__device__ __forceinline__ float gelu_f(float x) {
    return 0.5f * x * (1.0f + erff(x * 0.70710678118654752f));
}

__device__ __forceinline__ float tf32_rnd(float x) {
    uint32_t u;
    asm("cvt.rna.tf32.f32 %0, %1;" : "=r"(u) : "f"(x));
    return __uint_as_float(u);
}

__device__ __forceinline__ void mma_tf32(float* c, const uint32_t* a,
                                         uint32_t b0, uint32_t b1) {
    asm volatile(
        "mma.sync.aligned.m16n8k8.row.col.f32.tf32.tf32.f32 "
        "{%0,%1,%2,%3}, {%4,%5,%6,%7}, {%8,%9}, {%0,%1,%2,%3};\n"
        : "+f"(c[0]), "+f"(c[1]), "+f"(c[2]), "+f"(c[3])
        : "r"(a[0]), "r"(a[1]), "r"(a[2]), "r"(a[3]), "r"(b0), "r"(b1));
}

// ---------------- gather: x_in -> x_a, x_d (+ row means) ----------------
__global__ void gather_kernel(const float* __restrict__ x_in,
                              float* __restrict__ xa, float* __restrict__ xd,
                              float* __restrict__ mxa, float* __restrict__ mxd)
{
    int row = blockIdx.x;              // bt*196 + s
    int bt  = row / HWN, s = row % HWN;
    int b   = bt >> 3,  t2 = bt & 7;
    int tt  = t2 * 2;
    int nt_a = tt >> 2,     t_a = tt & 3;
    int nt_d = (tt+1) >> 2, t_d = (tt+1) & 3;
    size_t base_a = ((size_t)b*TOKENS + (size_t)nt_a*784 + s*4 + t_a) * CC;
    size_t base_d = ((size_t)b*TOKENS + (size_t)nt_d*784 + s*4 + t_d) * CC;

    float suma = 0.f, sumd = 0.f;
    int c4 = threadIdx.x * 4;
    if (c4 < CC) {
        float4 va = *(const float4*)&x_in[base_a + c4];
        float4 vd = *(const float4*)&x_in[base_d + c4];
        *(float4*)&xa[(size_t)row*CC + c4] = va;
        *(float4*)&xd[(size_t)row*CC + c4] = vd;
        suma = va.x+va.y+va.z+va.w;
        sumd = vd.x+vd.y+vd.z+vd.w;
    }
    __shared__ float ra[256], rd[256];
    ra[threadIdx.x] = suma; rd[threadIdx.x] = sumd;
    __syncthreads();
    for (int st = 128; st > 0; st >>= 1) {
        if (threadIdx.x < st) {
            ra[threadIdx.x] += ra[threadIdx.x + st];
            rd[threadIdx.x] += rd[threadIdx.x + st];
        }
        __syncthreads();
    }
    if (threadIdx.x == 0) {
        mxa[row] = ra[0] * (1.f/768.f);
        mxd[row] = rd[0] * (1.f/768.f);
    }
}

// ---------------- tf32 tensor-core GEMM: Y = epi(A @ W + bias) --------------
#define TBM 128
#define TBN 128
#define TBK 16
#define TP  136

#define EPI_BIAS     0
#define EPI_GELU     1
#define EPI_GELU_SUB 2

__global__ __launch_bounds__(256, 2) void gemm_tc(
    const float* __restrict__ A, const float* __restrict__ W,
    const float* __restrict__ bias, float* __restrict__ Y,
    const float* __restrict__ Xsub, int M, int N, int K, int epi)
{
    __shared__ float As[2][TBK][TP];
    __shared__ float Bs[2][TBK][TP];

    const int tid  = threadIdx.x;
    const int bm   = blockIdx.y * TBM;
    const int bn   = blockIdx.x * TBN;
    const int lane = tid & 31, warp = tid >> 5;
    const int wm   = (warp & 1) * 64;
    const int wn   = (warp >> 1) * 32;
    const int g    = lane >> 2;
    const int qp   = lane & 3;

    const int ar = tid >> 1;
    const int ac = (tid & 1) * 8;
    const int br = tid >> 4;
    const int bc = (tid & 15) * 8;

    const float* Ag = A + (size_t)(bm + ar) * K + ac;
    const float* Wg = W + (size_t)br * N + bn + bc;

    float acc[4][4][4];
    #pragma unroll
    for (int i=0;i<4;i++)
        #pragma unroll
        for (int j=0;j<4;j++)
            #pragma unroll
            for (int r=0;r<4;r++) acc[i][j][r]=0.f;

    {
        float4 a0 = *(const float4*)(Ag);
        float4 a1 = *(const float4*)(Ag + 4);
        As[0][ac+0][ar]=tf32_rnd(a0.x); As[0][ac+1][ar]=tf32_rnd(a0.y);
        As[0][ac+2][ar]=tf32_rnd(a0.z); As[0][ac+3][ar]=tf32_rnd(a0.w);
        As[0][ac+4][ar]=tf32_rnd(a1.x); As[0][ac+5][ar]=tf32_rnd(a1.y);
        As[0][ac+6][ar]=tf32_rnd(a1.z); As[0][ac+7][ar]=tf32_rnd(a1.w);
        float4 b0 = *(const float4*)(Wg);
        float4 b1 = *(const float4*)(Wg + 4);
        Bs[0][br][bc+0]=tf32_rnd(b0.x); Bs[0][br][bc+1]=tf32_rnd(b0.y);
        Bs[0][br][bc+2]=tf32_rnd(b0.z); Bs[0][br][bc+3]=tf32_rnd(b0.w);
        Bs[0][br][bc+4]=tf32_rnd(b1.x); Bs[0][br][bc+5]=tf32_rnd(b1.y);
        Bs[0][br][bc+6]=tf32_rnd(b1.z); Bs[0][br][bc+7]=tf32_rnd(b1.w);
    }
    __syncthreads();

    const int nk = K / TBK;
    for (int kt = 0; kt < nk; kt++) {
        const int cur = kt & 1;
        float4 na0, na1, nb0, nb1;
        const bool has_next = (kt + 1 < nk);
        if (has_next) {
            const float* Ag2 = Ag + (kt+1)*TBK;
            na0 = *(const float4*)(Ag2);
            na1 = *(const float4*)(Ag2 + 4);
            const float* Wg2 = Wg + (size_t)(kt+1)*TBK * N;
            nb0 = *(const float4*)(Wg2);
            nb1 = *(const float4*)(Wg2 + 4);
        }
        #pragma unroll
        for (int ks = 0; ks < 2; ks++) {
            const int kk = ks * 8;
            uint32_t af[4][4], bf[4][2];
            #pragma unroll
            for (int mi=0; mi<4; mi++) {
                int rb = wm + mi*16;
                af[mi][0] = __float_as_uint(As[cur][kk+qp  ][rb+g  ]);
                af[mi][1] = __float_as_uint(As[cur][kk+qp  ][rb+g+8]);
                af[mi][2] = __float_as_uint(As[cur][kk+qp+4][rb+g  ]);
                af[mi][3] = __float_as_uint(As[cur][kk+qp+4][rb+g+8]);
            }
            #pragma unroll
            for (int ni=0; ni<4; ni++) {
                int cb = wn + ni*8;
                bf[ni][0] = __float_as_uint(Bs[cur][kk+qp  ][cb+g]);
                bf[ni][1] = __float_as_uint(Bs[cur][kk+qp+4][cb+g]);
            }
            #pragma unroll
            for (int mi=0; mi<4; mi++)
                #pragma unroll
                for (int ni=0; ni<4; ni++)
                    mma_tf32(acc[mi][ni], af[mi], bf[ni][0], bf[ni][1]);
        }
        if (has_next) {
            const int nxt = cur ^ 1;
            As[nxt][ac+0][ar]=tf32_rnd(na0.x); As[nxt][ac+1][ar]=tf32_rnd(na0.y);
            As[nxt][ac+2][ar]=tf32_rnd(na0.z); As[nxt][ac+3][ar]=tf32_rnd(na0.w);
            As[nxt][ac+4][ar]=tf32_rnd(na1.x); As[nxt][ac+5][ar]=tf32_rnd(na1.y);
            As[nxt][ac+6][ar]=tf32_rnd(na1.z); As[nxt][ac+7][ar]=tf32_rnd(na1.w);
            Bs[nxt][br][bc+0]=tf32_rnd(nb0.x); Bs[nxt][br][bc+1]=tf32_rnd(nb0.y);
            Bs[nxt][br][bc+2]=tf32_rnd(nb0.z); Bs[nxt][br][bc+3]=tf32_rnd(nb0.w);
            Bs[nxt][br][bc+4]=tf32_rnd(nb1.x); Bs[nxt][br][bc+5]=tf32_rnd(nb1.y);
            Bs[nxt][br][bc+6]=tf32_rnd(nb1.z); Bs[nxt][br][bc+7]=tf32_rnd(nb1.w);
        }
        __syncthreads();
    }

    #pragma unroll
    for (int mi=0; mi<4; mi++) {
        const int r0 = bm + wm + mi*16 + g;
        const int r1 = r0 + 8;
        #pragma unroll
        for (int ni=0; ni<4; ni++) {
            const int c = bn + wn + ni*8 + qp*2;
            const float b0v = __ldg(&bias[c]);
            const float b1v = __ldg(&bias[c+1]);
            float v00 = acc[mi][ni][0] + b0v, v01 = acc[mi][ni][1] + b1v;
            float v10 = acc[mi][ni][2] + b0v, v11 = acc[mi][ni][3] + b1v;
            float2 o0, o1;
            if (epi == EPI_BIAS) {
                o0 = make_float2(v00, v01);
                o1 = make_float2(v10, v11);
            } else if (epi == EPI_GELU) {
                o0 = make_float2(gelu_f(v00), gelu_f(v01));
                o1 = make_float2(gelu_f(v10), gelu_f(v11));
            } else {
                float2 x0 = *(const float2*)&Xsub[(size_t)r0*N + c];
                float2 x1 = *(const float2*)&Xsub[(size_t)r1*N + c];
                o0 = make_float2(x0.x - gelu_f(v00), x0.y - gelu_f(v01));
                o1 = make_float2(x1.x - gelu_f(v10), x1.y - gelu_f(v11));
            }
            *(float2*)&Y[(size_t)r0*N + c] = o0;
            *(float2*)&Y[(size_t)r1*N + c] = o1;
        }
    }
}

// ---------------- tensor-core attention, one CTA per (bt, head) -------------
// 7 warps x 32 Q-rows (224 >= 196). S = QK^T and O = PV both on tf32 HMMA.
// No running-max softmax: scores are small (|s|<~3); clamp at 80 for safety.
// K in smem [200][KSP], V transposed [64][VTP], pitches chosen conflict-free.
#define AT_WARPS   7
#define AT_THREADS 224
#define KSP 68     // (g*68 + qp) % 32 = 4g+qp  -> conflict-free S B-frags
#define VTP 212    // ((8di+g)*212 + qp) % 32 = 20g+qp (mod 32 distinct)
#define PSP 9
#define ATTN_SMEM ((200*KSP + 64*VTP + AT_WARPS*32*PSP) * 4)

__global__ __launch_bounds__(AT_THREADS, 1) void attn_tc(
    const float* __restrict__ Q, const float* __restrict__ KV, float* __restrict__ O)
{
    extern __shared__ float sm[];
    float* Ks = sm;                       // [200][KSP]
    float* Vt = sm + 200*KSP;             // [64][VTP]
    float* Ps = Vt + 64*VTP;              // [7][32][PSP]

    const int bt = blockIdx.x / NHEAD;
    const int h  = blockIdx.x % NHEAD;
    const int tid  = threadIdx.x;
    const int w    = tid >> 5;
    const int lane = tid & 31;
    const int g    = lane >> 2;
    const int qp   = lane & 3;

    // ---- load K (tf32) and V (tf32, transposed) into smem ----
    const float* kvbase = KV + (size_t)bt * HWN * 1536 + h * HD;
    for (int idx = tid; idx < HWN * 16; idx += AT_THREADS) {
        int r = idx >> 4, c4 = (idx & 15) << 2;
        float4 kk = *(const float4*)&kvbase[(size_t)r*1536 + c4];
        Ks[r*KSP + c4+0] = tf32_rnd(kk.x);
        Ks[r*KSP + c4+1] = tf32_rnd(kk.y);
        Ks[r*KSP + c4+2] = tf32_rnd(kk.z);
        Ks[r*KSP + c4+3] = tf32_rnd(kk.w);
        float4 vv = *(const float4*)&kvbase[(size_t)r*1536 + 768 + c4];
        Vt[(c4+0)*VTP + r] = tf32_rnd(vv.x);
        Vt[(c4+1)*VTP + r] = tf32_rnd(vv.y);
        Vt[(c4+2)*VTP + r] = tf32_rnd(vv.z);
        Vt[(c4+3)*VTP + r] = tf32_rnd(vv.w);
    }
    // zero-pad keys 196..199
    for (int idx = tid; idx < 4*64; idx += AT_THREADS) {
        int r = 196 + (idx >> 6), d = idx & 63;
        Ks[r*KSP + d] = 0.f;
        Vt[d*VTP + r] = 0.f;
    }
    __syncthreads();

    // ---- Q fragments in registers (tf32) ----
    uint32_t qa[2][8][4];
    #pragma unroll
    for (int mi = 0; mi < 2; mi++) {
        int r0 = 32*w + 16*mi + g, r1 = r0 + 8;
        const float* q0 = Q + ((size_t)bt*HWN + r0)*CC + h*HD;
        const float* q1 = Q + ((size_t)bt*HWN + r1)*CC + h*HD;
        bool v0 = (r0 < HWN), v1 = (r1 < HWN);
        #pragma unroll
        for (int k = 0; k < 8; k++) {
            qa[mi][k][0] = v0 ? __float_as_uint(tf32_rnd(q0[8*k+qp  ])) : 0u;
            qa[mi][k][1] = v1 ? __float_as_uint(tf32_rnd(q1[8*k+qp  ])) : 0u;
            qa[mi][k][2] = v0 ? __float_as_uint(tf32_rnd(q0[8*k+qp+4])) : 0u;
            qa[mi][k][3] = v1 ? __float_as_uint(tf32_rnd(q1[8*k+qp+4])) : 0u;
        }
    }

    float oacc[2][8][4];
    #pragma unroll
    for (int mi=0; mi<2; mi++)
        #pragma unroll
        for (int di=0; di<8; di++)
            #pragma unroll
            for (int r=0; r<4; r++) oacc[mi][di][r] = 0.f;
    float lp[2][2] = {{0.f,0.f},{0.f,0.f}};
    float* Pw = Ps + w*32*PSP;

    // ---- main loop over key tiles (25 x 8 keys) ----
    for (int nt = 0; nt < 25; nt++) {
        const int j0 = nt * 8;
        float c[2][4] = {{0.f,0.f,0.f,0.f},{0.f,0.f,0.f,0.f}};
        const float* krow = &Ks[(j0+g)*KSP];
        #pragma unroll
        for (int k = 0; k < 8; k++) {
            uint32_t b0 = __float_as_uint(krow[8*k+qp  ]);
            uint32_t b1 = __float_as_uint(krow[8*k+qp+4]);
            mma_tf32(c[0], qa[0][k], b0, b1);
            mma_tf32(c[1], qa[1][k], b0, b1);
        }

        // softmax numerator (no max subtraction; clamp for safety) + stage P
        const int col0 = j0 + 2*qp;
        const bool m0 = (col0     < HWN);
        const bool m1 = (col0 + 1 < HWN);
        #pragma unroll
        for (int mi = 0; mi < 2; mi++) {
            float p00 = m0 ? __expf(fminf(c[mi][0]*SCALE_A, 80.f)) : 0.f;
            float p01 = m1 ? __expf(fminf(c[mi][1]*SCALE_A, 80.f)) : 0.f;
            float p10 = m0 ? __expf(fminf(c[mi][2]*SCALE_A, 80.f)) : 0.f;
            float p11 = m1 ? __expf(fminf(c[mi][3]*SCALE_A, 80.f)) : 0.f;
            lp[mi][0] += p00 + p01;
            lp[mi][1] += p10 + p11;
            Pw[(16*mi   + g)*PSP + 2*qp    ] = p00;
            Pw[(16*mi   + g)*PSP + 2*qp + 1] = p01;
            Pw[(16*mi+8 + g)*PSP + 2*qp    ] = p10;
            Pw[(16*mi+8 + g)*PSP + 2*qp + 1] = p11;
        }
        __syncwarp();

        uint32_t pa[2][4];
        #pragma unroll
        for (int mi = 0; mi < 2; mi++) {
            pa[mi][0] = __float_as_uint(Pw[(16*mi   + g)*PSP + qp  ]);
            pa[mi][1] = __float_as_uint(Pw[(16*mi+8 + g)*PSP + qp  ]);
            pa[mi][2] = __float_as_uint(Pw[(16*mi   + g)*PSP + qp+4]);
            pa[mi][3] = __float_as_uint(Pw[(16*mi+8 + g)*PSP + qp+4]);
        }
        __syncwarp();

        #pragma unroll
        for (int di = 0; di < 8; di++) {
            uint32_t b0 = __float_as_uint(Vt[(8*di+g)*VTP + j0+qp  ]);
            uint32_t b1 = __float_as_uint(Vt[(8*di+g)*VTP + j0+qp+4]);
            mma_tf32(oacc[0][di], pa[0], b0, b1);
            mma_tf32(oacc[1][di], pa[1], b0, b1);
        }
    }

    // ---- finalize: quad-reduce l, scale, store ----
    float inv[2][2];
    #pragma unroll
    for (int mi = 0; mi < 2; mi++)
        #pragma unroll
        for (int hf = 0; hf < 2; hf++) {
            float l = lp[mi][hf];
            l += __shfl_xor_sync(0xffffffffu, l, 1);
            l += __shfl_xor_sync(0xffffffffu, l, 2);
            inv[mi][hf] = 1.f / l;
        }

    #pragma unroll
    for (int mi = 0; mi < 2; mi++) {
        int r0 = 32*w + 16*mi + g, r1 = r0 + 8;
        float i0 = inv[mi][0], i1 = inv[mi][1];
        #pragma unroll
        for (int di = 0; di < 8; di++) {
            int c = h*HD + 8*di + 2*qp;
            if (r0 < HWN)
                *(float2*)&O[((size_t)bt*HWN + r0)*CC + c] =
                    make_float2(oacc[mi][di][0]*i0, oacc[mi][di][1]*i0);
            if (r1 < HWN)
                *(float2*)&O[((size_t)bt*HWN + r1)*CC + c] =
                    make_float2(oacc[mi][di][2]*i1, oacc[mi][di][3]*i1);
        }
    }
}

// ---------------- row mean over C=768 (one warp per row) --------------------
__global__ void rowmean_kernel(const float* __restrict__ X, float* __restrict__ out)
{
    int warp = threadIdx.x >> 5;
    int lane = threadIdx.x & 31;
    int row = blockIdx.x * 8 + warp;
    const float* p = X + (size_t)row * CC;
    float s = 0.f;
    #pragma unroll
    for (int k = 0; k < 6; k++) {
        float4 v = *(const float4*)&p[lane*4 + k*128];
        s += v.x + v.y + v.z + v.w;
    }
    #pragma unroll
    for (int off = 16; off; off >>= 1) s += __shfl_xor_sync(0xffffffffu, s, off);
    if (lane == 0) out[row] = s * (1.0f/768.0f);
}

// ---------------- final: pool_a assembly ------------------------------------
__global__ void final_kernel(const float* __restrict__ mxa, const float* __restrict__ mxd,
                             const float* __restrict__ mg2, float* __restrict__ out)
{
    int i = blockIdx.x * blockDim.x + threadIdx.x;
    if (i < ROWS) out[i] = 0.5f * (mxd[i] - mxa[i]) - mg2[i];
}

// ---------------- launch ----------------------------------------------------
extern "C" void kernel_launch(void* const* d_in, const int* in_sizes, int n_in,
                              void* d_out, int out_size)
{
    const float* x_in  = (const float*)d_in[0];
    const float* Wq_d  = (const float*)d_in[1];
    const float* bq_d  = (const float*)d_in[2];
    const float* Wkv_a = (const float*)d_in[3];
    const float* bkv_a = (const float*)d_in[4];
    const float* Wq_a  = (const float*)d_in[5];
    const float* bq_a  = (const float*)d_in[6];
    const float* Wkv_d = (const float*)d_in[7];
    const float* bkv_d = (const float*)d_in[8];
    const float* Wp_d  = (const float*)d_in[9];
    const float* bp_d  = (const float*)d_in[10];
    const float* Wp_a  = (const float*)d_in[11];
    const float* bp_a  = (const float*)d_in[12];
    float* out = (float*)d_out;

    float *xa, *xd, *xdn, *q, *kv, *o, *mxa, *mxd, *mg2;
    cudaGetSymbolAddress((void**)&xa,  g_xa);
    cudaGetSymbolAddress((void**)&xd,  g_xd);
    cudaGetSymbolAddress((void**)&xdn, g_xdn);
    cudaGetSymbolAddress((void**)&q,   g_q);
    cudaGetSymbolAddress((void**)&kv,  g_kv);
    cudaGetSymbolAddress((void**)&o,   g_o);
    cudaGetSymbolAddress((void**)&mxa, g_mxa);
    cudaGetSymbolAddress((void**)&mxd, g_mxd);
    cudaGetSymbolAddress((void**)&mg2, g_mg2);

    cudaFuncSetAttribute(attn_tc, cudaFuncAttributeMaxDynamicSharedMemorySize, ATTN_SMEM);

    dim3 g768(6, 196), g1536(12, 196);

    gather_kernel<<<ROWS, 256>>>(x_in, xa, xd, mxa, mxd);

    // ---- stage d: q from x_d, kv from x_a ----
    gemm_tc<<<g768,  256>>>(xd, Wq_d,  bq_d,  q,  nullptr, ROWS, 768,  768, EPI_BIAS);
    gemm_tc<<<g1536, 256>>>(xa, Wkv_a, bkv_a, kv, nullptr, ROWS, 1536, 768, EPI_BIAS);
    attn_tc<<<BT * NHEAD, AT_THREADS, ATTN_SMEM>>>(q, kv, o);
    gemm_tc<<<g768, 256>>>(o, Wp_d, bp_d, xdn, xd, ROWS, 768, 768, EPI_GELU_SUB);
    rowmean_kernel<<<ROWS/8, 256>>>(xdn, out + ROWS);

    // ---- stage a: q from x_a, kv from x_d_new ----
    gemm_tc<<<g768,  256>>>(xa,  Wq_a,  bq_a,  q,  nullptr, ROWS, 768,  768, EPI_BIAS);
    gemm_tc<<<g1536, 256>>>(xdn, Wkv_d, bkv_d, kv, nullptr, ROWS, 1536, 768, EPI_BIAS);
    attn_tc<<<BT * NHEAD, AT_THREADS, ATTN_SMEM>>>(q, kv, o);
    gemm_tc<<<g768, 256>>>(o, Wp_a, bp_a, xdn, nullptr, ROWS, 768, 768, EPI_GELU);
    rowmean_kernel<<<ROWS/8, 256>>>(xdn, mg2);

    final_kernel<<<(ROWS + 255)/256, 256>>>(mxa, mxd, mg2, out);
}

// round 5
// speedup vs baseline: 4.6292x; 1.5427x over previous
#include <cuda_runtime.h>
#include <cuda_bf16.h>
#include <math.h>
#include <stdint.h>

// ---------------- problem constants ----------------
#define NB      16
#define T2N     8
#define BT      128            // NB * T2N
#define HWN     196
#define ROWS    25088          // BT * HWN
#define CC      768
#define NHEAD   12
#define HD      64
#define SCALE_A 0.125f         // 1/sqrt(64)
#define TOKENS  3136

// ---------------- scratch (device globals; no allocs allowed) ----------------
__device__ float g_xa [25088u*768u];
__device__ float g_xd [25088u*768u];
__device__ float g_xdn[25088u*768u];
__device__ float g_q  [25088u*768u];
__device__ float g_kv [25088u*1536u];
__device__ float g_o  [25088u*768u];
__device__ float g_mxa[25088u];
__device__ float g_mxd[25088u];
__device__ float g_mg2[25088u];

__device__ __forceinline__ float gelu_f(float x) {
    return 0.5f * x * (1.0f + erff(x * 0.70710678118654752f));
}

__device__ __forceinline__ uint32_t pack_bf(float x, float y) {
    __nv_bfloat162 v = __float22bfloat162_rn(make_float2(x, y));
    return *reinterpret_cast<uint32_t*>(&v);
}

__device__ __forceinline__ void mma_bf16(float* c, const uint32_t* a,
                                         uint32_t b0, uint32_t b1) {
    asm volatile(
        "mma.sync.aligned.m16n8k16.row.col.f32.bf16.bf16.f32 "
        "{%0,%1,%2,%3}, {%4,%5,%6,%7}, {%8,%9}, {%0,%1,%2,%3};\n"
        : "+f"(c[0]), "+f"(c[1]), "+f"(c[2]), "+f"(c[3])
        : "r"(a[0]), "r"(a[1]), "r"(a[2]), "r"(a[3]), "r"(b0), "r"(b1));
}

// ---------------- gather: x_in -> x_a, x_d (+ row means) ----------------
__global__ void gather_kernel(const float* __restrict__ x_in,
                              float* __restrict__ xa, float* __restrict__ xd,
                              float* __restrict__ mxa, float* __restrict__ mxd)
{
    int row = blockIdx.x;              // bt*196 + s
    int bt  = row / HWN, s = row % HWN;
    int b   = bt >> 3,  t2 = bt & 7;
    int tt  = t2 * 2;
    int nt_a = tt >> 2,     t_a = tt & 3;
    int nt_d = (tt+1) >> 2, t_d = (tt+1) & 3;
    size_t base_a = ((size_t)b*TOKENS + (size_t)nt_a*784 + s*4 + t_a) * CC;
    size_t base_d = ((size_t)b*TOKENS + (size_t)nt_d*784 + s*4 + t_d) * CC;

    float suma = 0.f, sumd = 0.f;
    int c4 = threadIdx.x * 4;
    if (c4 < CC) {
        float4 va = *(const float4*)&x_in[base_a + c4];
        float4 vd = *(const float4*)&x_in[base_d + c4];
        *(float4*)&xa[(size_t)row*CC + c4] = va;
        *(float4*)&xd[(size_t)row*CC + c4] = vd;
        suma = va.x+va.y+va.z+va.w;
        sumd = vd.x+vd.y+vd.z+vd.w;
    }
    __shared__ float ra[256], rd[256];
    ra[threadIdx.x] = suma; rd[threadIdx.x] = sumd;
    __syncthreads();
    for (int st = 128; st > 0; st >>= 1) {
        if (threadIdx.x < st) {
            ra[threadIdx.x] += ra[threadIdx.x + st];
            rd[threadIdx.x] += rd[threadIdx.x + st];
        }
        __syncthreads();
    }
    if (threadIdx.x == 0) {
        mxa[row] = ra[0] * (1.f/768.f);
        mxd[row] = rd[0] * (1.f/768.f);
    }
}

// ---------------- bf16 tensor-core GEMM: Y = epi(A @ W + bias) --------------
// A: MxK row-major fp32, W: KxN row-major fp32. Block 128x128x16, 8 warps,
// warp tile 64x32 via mma.m16n8k16.bf16 (fp32 accum). Smem holds k-packed
// bf16x2 (u32). Double-buffered. One MMA k-step per 16-deep tile.
#define TBM 128
#define TBN 128
#define TBK 16
#define TPu 136    // u32 pitch; (qp*136+g) % 32 = 8qp+g -> conflict-free

#define EPI_BIAS     0
#define EPI_GELU     1
#define EPI_GELU_SUB 2

__global__ __launch_bounds__(256, 2) void gemm_tc(
    const float* __restrict__ A, const float* __restrict__ W,
    const float* __restrict__ bias, float* __restrict__ Y,
    const float* __restrict__ Xsub, int M, int N, int K, int epi)
{
    __shared__ uint32_t As[2][8][TPu];   // [kpair][m]
    __shared__ uint32_t Bs[2][8][TPu];   // [kpair][n]

    const int tid  = threadIdx.x;
    const int bm   = blockIdx.y * TBM;
    const int bn   = blockIdx.x * TBN;
    const int lane = tid & 31, warp = tid >> 5;
    const int wm   = (warp & 1) * 64;
    const int wn   = (warp >> 1) * 32;
    const int g    = lane >> 2;
    const int qp   = lane & 3;

    // global load mapping
    const int ar  = tid >> 1;            // 0..127 (m row)
    const int ac  = (tid & 1) * 8;       // k: 0 or 8
    const int bk  = (tid >> 5) * 2;      // k row pair base: 0,2,..,14
    const int bn0 = (tid & 31) * 4;      // n: 0..124

    const float* Ag = A + (size_t)(bm + ar) * K + ac;
    const float* Wg = W + (size_t)bk * N + bn + bn0;

    float acc[4][4][4];
    #pragma unroll
    for (int i=0;i<4;i++)
        #pragma unroll
        for (int j=0;j<4;j++)
            #pragma unroll
            for (int r=0;r<4;r++) acc[i][j][r]=0.f;

    // prologue: load tile 0
    {
        float4 a0 = *(const float4*)(Ag);
        float4 a1 = *(const float4*)(Ag + 4);
        As[0][ac/2+0][ar] = pack_bf(a0.x, a0.y);
        As[0][ac/2+1][ar] = pack_bf(a0.z, a0.w);
        As[0][ac/2+2][ar] = pack_bf(a1.x, a1.y);
        As[0][ac/2+3][ar] = pack_bf(a1.z, a1.w);
        float4 b0 = *(const float4*)(Wg);
        float4 b1 = *(const float4*)(Wg + N);
        Bs[0][bk/2][bn0+0] = pack_bf(b0.x, b1.x);
        Bs[0][bk/2][bn0+1] = pack_bf(b0.y, b1.y);
        Bs[0][bk/2][bn0+2] = pack_bf(b0.z, b1.z);
        Bs[0][bk/2][bn0+3] = pack_bf(b0.w, b1.w);
    }
    __syncthreads();

    const int nk = K / TBK;
    for (int kt = 0; kt < nk; kt++) {
        const int cur = kt & 1;
        float4 na0, na1, nb0, nb1;
        const bool has_next = (kt + 1 < nk);
        if (has_next) {
            const float* Ag2 = Ag + (kt+1)*TBK;
            na0 = *(const float4*)(Ag2);
            na1 = *(const float4*)(Ag2 + 4);
            const float* Wg2 = Wg + (size_t)(kt+1)*TBK * N;
            nb0 = *(const float4*)(Wg2);
            nb1 = *(const float4*)(Wg2 + N);
        }
        // fragments + 16 MMAs (single k16 step covers the whole tile)
        uint32_t af[4][4], bf[4][2];
        #pragma unroll
        for (int mi=0; mi<4; mi++) {
            int rb = wm + mi*16;
            af[mi][0] = As[cur][qp  ][rb+g  ];
            af[mi][1] = As[cur][qp  ][rb+g+8];
            af[mi][2] = As[cur][qp+4][rb+g  ];
            af[mi][3] = As[cur][qp+4][rb+g+8];
        }
        #pragma unroll
        for (int ni=0; ni<4; ni++) {
            int cb = wn + ni*8;
            bf[ni][0] = Bs[cur][qp  ][cb+g];
            bf[ni][1] = Bs[cur][qp+4][cb+g];
        }
        #pragma unroll
        for (int mi=0; mi<4; mi++)
            #pragma unroll
            for (int ni=0; ni<4; ni++)
                mma_bf16(acc[mi][ni], af[mi], bf[ni][0], bf[ni][1]);

        if (has_next) {
            const int nxt = cur ^ 1;
            As[nxt][ac/2+0][ar] = pack_bf(na0.x, na0.y);
            As[nxt][ac/2+1][ar] = pack_bf(na0.z, na0.w);
            As[nxt][ac/2+2][ar] = pack_bf(na1.x, na1.y);
            As[nxt][ac/2+3][ar] = pack_bf(na1.z, na1.w);
            Bs[nxt][bk/2][bn0+0] = pack_bf(nb0.x, nb1.x);
            Bs[nxt][bk/2][bn0+1] = pack_bf(nb0.y, nb1.y);
            Bs[nxt][bk/2][bn0+2] = pack_bf(nb0.z, nb1.z);
            Bs[nxt][bk/2][bn0+3] = pack_bf(nb0.w, nb1.w);
        }
        __syncthreads();
    }

    // epilogue
    #pragma unroll
    for (int mi=0; mi<4; mi++) {
        const int r0 = bm + wm + mi*16 + g;
        const int r1 = r0 + 8;
        #pragma unroll
        for (int ni=0; ni<4; ni++) {
            const int c = bn + wn + ni*8 + qp*2;
            const float b0v = __ldg(&bias[c]);
            const float b1v = __ldg(&bias[c+1]);
            float v00 = acc[mi][ni][0] + b0v, v01 = acc[mi][ni][1] + b1v;
            float v10 = acc[mi][ni][2] + b0v, v11 = acc[mi][ni][3] + b1v;
            float2 o0, o1;
            if (epi == EPI_BIAS) {
                o0 = make_float2(v00, v01);
                o1 = make_float2(v10, v11);
            } else if (epi == EPI_GELU) {
                o0 = make_float2(gelu_f(v00), gelu_f(v01));
                o1 = make_float2(gelu_f(v10), gelu_f(v11));
            } else {
                float2 x0 = *(const float2*)&Xsub[(size_t)r0*N + c];
                float2 x1 = *(const float2*)&Xsub[(size_t)r1*N + c];
                o0 = make_float2(x0.x - gelu_f(v00), x0.y - gelu_f(v01));
                o1 = make_float2(x1.x - gelu_f(v10), x1.y - gelu_f(v11));
            }
            *(float2*)&Y[(size_t)r0*N + c] = o0;
            *(float2*)&Y[(size_t)r1*N + c] = o1;
        }
    }
}

// ---------------- bf16 tensor-core attention, one CTA per (bt, head) --------
// 7 warps x 32 Q-rows. Keys padded to 208; 13 tiles of 16 keys. S and PV on
// mma.m16n8k16.bf16. No running max (scores bounded; clamp 80).
// Smem (u32): K [208][36] pairs-along-dim; V^T [64][116] pairs-along-key;
// P stage [7][32][12] pairs-along-key. All fragment reads conflict-free.
#define AT_WARPS   7
#define AT_THREADS 224
#define NKP 208
#define KSP2 36
#define VTP2 116
#define PPu  12
#define ATTN_SMEM ((NKP*KSP2 + 64*VTP2 + AT_WARPS*32*PPu) * 4)

__global__ __launch_bounds__(AT_THREADS, 2) void attn_tc(
    const float* __restrict__ Q, const float* __restrict__ KV, float* __restrict__ O)
{
    extern __shared__ uint32_t smu[];
    uint32_t* Ks = smu;                    // [208][36]
    uint32_t* Vt = smu + NKP*KSP2;         // [64][116]
    uint32_t* Ps = Vt + 64*VTP2;           // [7][32][12]

    const int bt = blockIdx.x / NHEAD;
    const int h  = blockIdx.x % NHEAD;
    const int tid  = threadIdx.x;
    const int w    = tid >> 5;
    const int lane = tid & 31;
    const int g    = lane >> 2;
    const int qp   = lane & 3;

    // ---- load K (pairs along dim) and V^T (pairs along key) ----
    const float* kvbase = KV + (size_t)bt * HWN * 1536 + h * HD;
    __nv_bfloat16* Vb = reinterpret_cast<__nv_bfloat16*>(Vt);
    for (int idx = tid; idx < HWN * 16; idx += AT_THREADS) {
        int r = idx >> 4, c4 = (idx & 15) << 2;
        float4 kk = *(const float4*)&kvbase[(size_t)r*1536 + c4];
        Ks[r*KSP2 + c4/2    ] = pack_bf(kk.x, kk.y);
        Ks[r*KSP2 + c4/2 + 1] = pack_bf(kk.z, kk.w);
        float4 vv = *(const float4*)&kvbase[(size_t)r*1536 + 768 + c4];
        int vbase = (r >> 1) * 2 + (r & 1);   // bf16 index within pair row
        Vb[(c4+0)*VTP2*2 + vbase] = __float2bfloat16_rn(vv.x);
        Vb[(c4+1)*VTP2*2 + vbase] = __float2bfloat16_rn(vv.y);
        Vb[(c4+2)*VTP2*2 + vbase] = __float2bfloat16_rn(vv.z);
        Vb[(c4+3)*VTP2*2 + vbase] = __float2bfloat16_rn(vv.w);
    }
    // zero-pad: K rows 196..207, V key-pairs 98..103 (keys 196..207)
    for (int idx = tid; idx < 12*KSP2; idx += AT_THREADS)
        Ks[(196 + idx/KSP2)*KSP2 + idx%KSP2] = 0u;
    for (int idx = tid; idx < 64*6; idx += AT_THREADS)
        Vt[(idx/6)*VTP2 + 98 + idx%6] = 0u;
    __syncthreads();

    // ---- Q fragments (bf16) in registers ----
    uint32_t qa[2][4][4];
    #pragma unroll
    for (int mi = 0; mi < 2; mi++) {
        int r0 = 32*w + 16*mi + g, r1 = r0 + 8;
        const float* q0 = Q + ((size_t)bt*HWN + r0)*CC + h*HD;
        const float* q1 = Q + ((size_t)bt*HWN + r1)*CC + h*HD;
        bool v0 = (r0 < HWN), v1 = (r1 < HWN);
        #pragma unroll
        for (int kk = 0; kk < 4; kk++) {
            float2 x0a = v0 ? *(const float2*)&q0[16*kk + 2*qp    ] : make_float2(0,0);
            float2 x0b = v0 ? *(const float2*)&q0[16*kk + 2*qp + 8] : make_float2(0,0);
            float2 x1a = v1 ? *(const float2*)&q1[16*kk + 2*qp    ] : make_float2(0,0);
            float2 x1b = v1 ? *(const float2*)&q1[16*kk + 2*qp + 8] : make_float2(0,0);
            qa[mi][kk][0] = pack_bf(x0a.x, x0a.y);
            qa[mi][kk][1] = pack_bf(x1a.x, x1a.y);
            qa[mi][kk][2] = pack_bf(x0b.x, x0b.y);
            qa[mi][kk][3] = pack_bf(x1b.x, x1b.y);
        }
    }

    float oacc[2][8][4];
    #pragma unroll
    for (int mi=0; mi<2; mi++)
        #pragma unroll
        for (int di=0; di<8; di++)
            #pragma unroll
            for (int r=0; r<4; r++) oacc[mi][di][r] = 0.f;
    float lp[2][2] = {{0.f,0.f},{0.f,0.f}};
    uint32_t* Pw = Ps + w*32*PPu;

    // ---- main loop: 13 tiles of 16 keys ----
    for (int nt = 0; nt < 13; nt++) {
        const int j0 = nt * 16;
        float c[2][2][4];   // [mi][hf][4]
        #pragma unroll
        for (int mi=0;mi<2;mi++)
            #pragma unroll
            for (int hf=0;hf<2;hf++)
                #pragma unroll
                for (int r=0;r<4;r++) c[mi][hf][r]=0.f;

        #pragma unroll
        for (int kk = 0; kk < 4; kk++) {
            #pragma unroll
            for (int hf = 0; hf < 2; hf++) {
                const uint32_t* kr = &Ks[(j0 + 8*hf + g)*KSP2];
                uint32_t b0 = kr[8*kk + qp    ];
                uint32_t b1 = kr[8*kk + qp + 4];
                mma_bf16(c[0][hf], qa[0][kk], b0, b1);
                mma_bf16(c[1][hf], qa[1][kk], b0, b1);
            }
        }

        // exp (masked) + pack P into smem as bf16 key-pairs
        #pragma unroll
        for (int mi = 0; mi < 2; mi++) {
            #pragma unroll
            for (int hf = 0; hf < 2; hf++) {
                const int col0 = j0 + 8*hf + 2*qp;
                const bool m0 = (col0     < HWN);
                const bool m1 = (col0 + 1 < HWN);
                float p00 = m0 ? __expf(fminf(c[mi][hf][0]*SCALE_A, 80.f)) : 0.f;
                float p01 = m1 ? __expf(fminf(c[mi][hf][1]*SCALE_A, 80.f)) : 0.f;
                float p10 = m0 ? __expf(fminf(c[mi][hf][2]*SCALE_A, 80.f)) : 0.f;
                float p11 = m1 ? __expf(fminf(c[mi][hf][3]*SCALE_A, 80.f)) : 0.f;
                lp[mi][0] += p00 + p01;
                lp[mi][1] += p10 + p11;
                Pw[(16*mi   + g)*PPu + 4*hf + qp] = pack_bf(p00, p01);
                Pw[(16*mi+8 + g)*PPu + 4*hf + qp] = pack_bf(p10, p11);
            }
        }
        __syncwarp();

        uint32_t pa[2][4];
        #pragma unroll
        for (int mi = 0; mi < 2; mi++) {
            pa[mi][0] = Pw[(16*mi   + g)*PPu + qp    ];
            pa[mi][1] = Pw[(16*mi+8 + g)*PPu + qp    ];
            pa[mi][2] = Pw[(16*mi   + g)*PPu + qp + 4];
            pa[mi][3] = Pw[(16*mi+8 + g)*PPu + qp + 4];
        }
        __syncwarp();

        const int jp = nt * 8;   // key-pair base
        #pragma unroll
        for (int di = 0; di < 8; di++) {
            const uint32_t* vr = &Vt[(8*di + g)*VTP2 + jp];
            uint32_t b0 = vr[qp    ];
            uint32_t b1 = vr[qp + 4];
            mma_bf16(oacc[0][di], pa[0], b0, b1);
            mma_bf16(oacc[1][di], pa[1], b0, b1);
        }
    }

    // ---- finalize: quad-reduce l, scale, store ----
    float inv[2][2];
    #pragma unroll
    for (int mi = 0; mi < 2; mi++)
        #pragma unroll
        for (int hf = 0; hf < 2; hf++) {
            float l = lp[mi][hf];
            l += __shfl_xor_sync(0xffffffffu, l, 1);
            l += __shfl_xor_sync(0xffffffffu, l, 2);
            inv[mi][hf] = 1.f / l;
        }

    #pragma unroll
    for (int mi = 0; mi < 2; mi++) {
        int r0 = 32*w + 16*mi + g, r1 = r0 + 8;
        float i0 = inv[mi][0], i1 = inv[mi][1];
        #pragma unroll
        for (int di = 0; di < 8; di++) {
            int c = h*HD + 8*di + 2*qp;
            if (r0 < HWN)
                *(float2*)&O[((size_t)bt*HWN + r0)*CC + c] =
                    make_float2(oacc[mi][di][0]*i0, oacc[mi][di][1]*i0);
            if (r1 < HWN)
                *(float2*)&O[((size_t)bt*HWN + r1)*CC + c] =
                    make_float2(oacc[mi][di][2]*i1, oacc[mi][di][3]*i1);
        }
    }
}

// ---------------- row mean over C=768 (one warp per row) --------------------
__global__ void rowmean_kernel(const float* __restrict__ X, float* __restrict__ out)
{
    int warp = threadIdx.x >> 5;
    int lane = threadIdx.x & 31;
    int row = blockIdx.x * 8 + warp;
    const float* p = X + (size_t)row * CC;
    float s = 0.f;
    #pragma unroll
    for (int k = 0; k < 6; k++) {
        float4 v = *(const float4*)&p[lane*4 + k*128];
        s += v.x + v.y + v.z + v.w;
    }
    #pragma unroll
    for (int off = 16; off; off >>= 1) s += __shfl_xor_sync(0xffffffffu, s, off);
    if (lane == 0) out[row] = s * (1.0f/768.0f);
}

// ---------------- final: pool_a assembly ------------------------------------
__global__ void final_kernel(const float* __restrict__ mxa, const float* __restrict__ mxd,
                             const float* __restrict__ mg2, float* __restrict__ out)
{
    int i = blockIdx.x * blockDim.x + threadIdx.x;
    if (i < ROWS) out[i] = 0.5f * (mxd[i] - mxa[i]) - mg2[i];
}

// ---------------- launch ----------------------------------------------------
extern "C" void kernel_launch(void* const* d_in, const int* in_sizes, int n_in,
                              void* d_out, int out_size)
{
    const float* x_in  = (const float*)d_in[0];
    const float* Wq_d  = (const float*)d_in[1];
    const float* bq_d  = (const float*)d_in[2];
    const float* Wkv_a = (const float*)d_in[3];
    const float* bkv_a = (const float*)d_in[4];
    const float* Wq_a  = (const float*)d_in[5];
    const float* bq_a  = (const float*)d_in[6];
    const float* Wkv_d = (const float*)d_in[7];
    const float* bkv_d = (const float*)d_in[8];
    const float* Wp_d  = (const float*)d_in[9];
    const float* bp_d  = (const float*)d_in[10];
    const float* Wp_a  = (const float*)d_in[11];
    const float* bp_a  = (const float*)d_in[12];
    float* out = (float*)d_out;

    float *xa, *xd, *xdn, *q, *kv, *o, *mxa, *mxd, *mg2;
    cudaGetSymbolAddress((void**)&xa,  g_xa);
    cudaGetSymbolAddress((void**)&xd,  g_xd);
    cudaGetSymbolAddress((void**)&xdn, g_xdn);
    cudaGetSymbolAddress((void**)&q,   g_q);
    cudaGetSymbolAddress((void**)&kv,  g_kv);
    cudaGetSymbolAddress((void**)&o,   g_o);
    cudaGetSymbolAddress((void**)&mxa, g_mxa);
    cudaGetSymbolAddress((void**)&mxd, g_mxd);
    cudaGetSymbolAddress((void**)&mg2, g_mg2);

    cudaFuncSetAttribute(attn_tc, cudaFuncAttributeMaxDynamicSharedMemorySize, ATTN_SMEM);

    dim3 g768(6, 196), g1536(12, 196);

    gather_kernel<<<ROWS, 256>>>(x_in, xa, xd, mxa, mxd);

    // ---- stage d: q from x_d, kv from x_a ----
    gemm_tc<<<g768,  256>>>(xd, Wq_d,  bq_d,  q,  nullptr, ROWS, 768,  768, EPI_BIAS);
    gemm_tc<<<g1536, 256>>>(xa, Wkv_a, bkv_a, kv, nullptr, ROWS, 1536, 768, EPI_BIAS);
    attn_tc<<<BT * NHEAD, AT_THREADS, ATTN_SMEM>>>(q, kv, o);
    gemm_tc<<<g768, 256>>>(o, Wp_d, bp_d, xdn, xd, ROWS, 768, 768, EPI_GELU_SUB);
    rowmean_kernel<<<ROWS/8, 256>>>(xdn, out + ROWS);

    // ---- stage a: q from x_a, kv from x_d_new ----
    gemm_tc<<<g768,  256>>>(xa,  Wq_a,  bq_a,  q,  nullptr, ROWS, 768,  768, EPI_BIAS);
    gemm_tc<<<g1536, 256>>>(xdn, Wkv_d, bkv_d, kv, nullptr, ROWS, 1536, 768, EPI_BIAS);
    attn_tc<<<BT * NHEAD, AT_THREADS, ATTN_SMEM>>>(q, kv, o);
    gemm_tc<<<g768, 256>>>(o, Wp_a, bp_a, xdn, nullptr, ROWS, 768, 768, EPI_GELU);
    rowmean_kernel<<<ROWS/8, 256>>>(xdn, mg2);

    final_kernel<<<(ROWS + 255)/256, 256>>>(mxa, mxd, mg2, out);
}

// round 6
// speedup vs baseline: 6.1666x; 1.3321x over previous
#include <cuda_runtime.h>
#include <cuda_bf16.h>
#include <math.h>
#include <stdint.h>

// ---------------- problem constants ----------------
#define NB      16
#define BT      128            // NB * 8
#define HWN     196
#define ROWS    25088          // BT * HWN
#define CC      768
#define NHEAD   12
#define HD      64
#define SCALE_A 0.125f         // 1/sqrt(64)
#define TOKENS  3136

// ---------------- scratch (device globals; no allocs allowed) ----------------
__device__ __align__(16) __nv_bfloat16 g_xab [25088u*768u];
__device__ __align__(16) __nv_bfloat16 g_xdb [25088u*768u];
__device__ __align__(16) __nv_bfloat16 g_xdnb[25088u*768u];
__device__ __align__(16) __nv_bfloat16 g_qb  [25088u*768u];
__device__ __align__(16) __nv_bfloat16 g_kvb [25088u*1536u];
__device__ __align__(16) __nv_bfloat16 g_ob  [25088u*768u];
__device__ float g_xd [25088u*768u];   // fp32 x_d (Xsub for gelu-sub)
__device__ float g_xdn[25088u*768u];   // fp32 x_d_new / G2 (rowmean source)
__device__ __align__(16) uint32_t g_wp[2359296u];  // packed bf16x2 weights
__device__ float g_mxa[25088u];
__device__ float g_mxd[25088u];
__device__ float g_mg2[25088u];

__device__ __forceinline__ float gelu_f(float x) {
    return 0.5f * x * (1.0f + erff(x * 0.70710678118654752f));
}

__device__ __forceinline__ uint32_t pack_bf(float x, float y) {
    __nv_bfloat162 v = __float22bfloat162_rn(make_float2(x, y));
    return *reinterpret_cast<uint32_t*>(&v);
}

__device__ __forceinline__ void mma_bf16(float* c, const uint32_t* a,
                                         uint32_t b0, uint32_t b1) {
    asm volatile(
        "mma.sync.aligned.m16n8k16.row.col.f32.bf16.bf16.f32 "
        "{%0,%1,%2,%3}, {%4,%5,%6,%7}, {%8,%9}, {%0,%1,%2,%3};\n"
        : "+f"(c[0]), "+f"(c[1]), "+f"(c[2]), "+f"(c[3])
        : "r"(a[0]), "r"(a[1]), "r"(a[2]), "r"(a[3]), "r"(b0), "r"(b1));
}

__device__ __forceinline__ void cp16(uint32_t saddr, const void* g) {
    asm volatile("cp.async.ca.shared.global [%0], [%1], 16;\n"
                 :: "r"(saddr), "l"(g));
}

// ---------------- weight pre-pack: W[K][N] f32 -> Wp[K/2][N] bf16x2 ---------
__global__ void packw_kernel(const float* __restrict__ W, uint32_t* __restrict__ Wp,
                             int KH, int N)
{
    int i = blockIdx.x * 256 + threadIdx.x;
    if (i >= KH * N) return;
    int kp = i / N, n = i - kp * N;
    Wp[i] = pack_bf(W[(size_t)(2*kp) * N + n], W[(size_t)(2*kp+1) * N + n]);
}

// ---------------- gather: x_in -> xa_b, xd_b, xd_f32 (+ row means) ----------
__global__ void gather_kernel(const float* __restrict__ x_in,
                              __nv_bfloat16* __restrict__ xab,
                              __nv_bfloat16* __restrict__ xdb,
                              float* __restrict__ xd,
                              float* __restrict__ mxa, float* __restrict__ mxd)
{
    int row = blockIdx.x;              // bt*196 + s
    int bt  = row / HWN, s = row % HWN;
    int b   = bt >> 3,  t2 = bt & 7;
    int tt  = t2 * 2;
    int nt_a = tt >> 2,     t_a = tt & 3;
    int nt_d = (tt+1) >> 2, t_d = (tt+1) & 3;
    size_t base_a = ((size_t)b*TOKENS + (size_t)nt_a*784 + s*4 + t_a) * CC;
    size_t base_d = ((size_t)b*TOKENS + (size_t)nt_d*784 + s*4 + t_d) * CC;

    float suma = 0.f, sumd = 0.f;
    int c4 = threadIdx.x * 4;
    if (c4 < CC) {
        float4 va = *(const float4*)&x_in[base_a + c4];
        float4 vd = *(const float4*)&x_in[base_d + c4];
        uint2 pa; pa.x = pack_bf(va.x, va.y); pa.y = pack_bf(va.z, va.w);
        uint2 pd; pd.x = pack_bf(vd.x, vd.y); pd.y = pack_bf(vd.z, vd.w);
        *(uint2*)&xab[(size_t)row*CC + c4] = pa;
        *(uint2*)&xdb[(size_t)row*CC + c4] = pd;
        *(float4*)&xd[(size_t)row*CC + c4] = vd;
        suma = va.x+va.y+va.z+va.w;
        sumd = vd.x+vd.y+vd.z+vd.w;
    }
    __shared__ float ra[256], rd[256];
    ra[threadIdx.x] = suma; rd[threadIdx.x] = sumd;
    __syncthreads();
    for (int st = 128; st > 0; st >>= 1) {
        if (threadIdx.x < st) {
            ra[threadIdx.x] += ra[threadIdx.x + st];
            rd[threadIdx.x] += rd[threadIdx.x + st];
        }
        __syncthreads();
    }
    if (threadIdx.x == 0) {
        mxa[row] = ra[0] * (1.f/768.f);
        mxd[row] = rd[0] * (1.f/768.f);
    }
}

// ---------------- bf16 GEMM, cp.async 4-stage, TBK=32 -----------------------
// A: MxK bf16 row-major. Wp: [K/2][N] u32 (bf16x2 k-pairs). Block 128x128,
// 8 warps, warp tile 64x32, mma.m16n8k16. One barrier per 32-deep k-tile.
#define APITCH 20                    // u32 pitch, 16 data + 4 pad
#define BPITCH 132                   // u32 pitch, 128 data + 4 pad
#define A_STG  (128*APITCH)          // 2560 u32
#define B_STG  (16*BPITCH)           // 2112 u32
#define STG_U32 (A_STG + B_STG)      // 4672 u32
#define GEMM_SMEM (4 * STG_U32 * 4)  // 74752 B

#define EPI_BIAS     0
#define EPI_GELU     1
#define EPI_GELU_SUB 2

__global__ __launch_bounds__(256, 2) void gemm_bf(
    const __nv_bfloat16* __restrict__ A, const uint32_t* __restrict__ Wp,
    const float* __restrict__ bias,
    __nv_bfloat16* __restrict__ Yb, float* __restrict__ Yf,
    const float* __restrict__ Xsub, int M, int N, int K, int epi)
{
    extern __shared__ uint32_t smg[];
    const uint32_t sbase = (uint32_t)__cvta_generic_to_shared(smg);

    const int tid  = threadIdx.x;
    const int bm   = blockIdx.y * 128;
    const int bn   = blockIdx.x * 128;
    const int lane = tid & 31, warp = tid >> 5;
    const int wm   = (warp & 1) * 64;
    const int wn   = (warp >> 1) * 32;
    const int g    = lane >> 3 ? (lane >> 2) : (lane >> 2);  // g = lane>>2
    const int gg   = lane >> 2;
    const int qp   = lane & 3;
    (void)g;

    const int nk = K / 32;

    float acc[4][4][4];
    #pragma unroll
    for (int i=0;i<4;i++)
        #pragma unroll
        for (int j=0;j<4;j++)
            #pragma unroll
            for (int r=0;r<4;r++) acc[i][j][r]=0.f;

    // cp.async issue for k-tile kt into stage kt&3
    auto issue = [&](int kt) {
        const int stg = kt & 3;
        const uint32_t sa = sbase + (stg * STG_U32) * 4;
        #pragma unroll
        for (int c = tid; c < 512; c += 256) {      // A: 512 16B chunks
            int row = c >> 2, k8 = (c & 3) * 8;
            cp16(sa + (row * APITCH + (c & 3) * 4) * 4,
                 &A[(size_t)(bm + row) * K + kt*32 + k8]);
        }
        const uint32_t sb = sa + A_STG * 4;
        #pragma unroll
        for (int c = tid; c < 512; c += 256) {      // B: 512 16B chunks
            int kp = c >> 5, n4 = (c & 31) * 4;
            cp16(sb + (kp * BPITCH + n4) * 4,
                 &Wp[(size_t)(kt*16 + kp) * N + bn + n4]);
        }
        asm volatile("cp.async.commit_group;\n" ::: "memory");
    };

    issue(0); issue(1); issue(2);

    for (int kt = 0; kt < nk; kt++) {
        asm volatile("cp.async.wait_group 2;\n" ::: "memory");
        __syncthreads();
        if (kt + 3 < nk) issue(kt + 3);

        const uint32_t* As_ = smg + (kt & 3) * STG_U32;
        const uint32_t* Bs_ = As_ + A_STG;

        #pragma unroll
        for (int kk = 0; kk < 2; kk++) {
            uint32_t af[4][4], bf[4][2];
            #pragma unroll
            for (int mi = 0; mi < 4; mi++) {
                int rb = wm + mi*16;
                af[mi][0] = As_[(rb+gg  )*APITCH + kk*8 + qp    ];
                af[mi][1] = As_[(rb+gg+8)*APITCH + kk*8 + qp    ];
                af[mi][2] = As_[(rb+gg  )*APITCH + kk*8 + qp + 4];
                af[mi][3] = As_[(rb+gg+8)*APITCH + kk*8 + qp + 4];
            }
            #pragma unroll
            for (int ni = 0; ni < 4; ni++) {
                int cb = wn + ni*8;
                bf[ni][0] = Bs_[(kk*8 + qp    )*BPITCH + cb + gg];
                bf[ni][1] = Bs_[(kk*8 + qp + 4)*BPITCH + cb + gg];
            }
            #pragma unroll
            for (int mi = 0; mi < 4; mi++)
                #pragma unroll
                for (int ni = 0; ni < 4; ni++)
                    mma_bf16(acc[mi][ni], af[mi], bf[ni][0], bf[ni][1]);
        }
        __syncthreads();
    }

    // epilogue
    #pragma unroll
    for (int mi=0; mi<4; mi++) {
        const int r0 = bm + wm + mi*16 + gg;
        const int r1 = r0 + 8;
        #pragma unroll
        for (int ni=0; ni<4; ni++) {
            const int c = bn + wn + ni*8 + qp*2;
            const float b0v = __ldg(&bias[c]);
            const float b1v = __ldg(&bias[c+1]);
            float v00 = acc[mi][ni][0] + b0v, v01 = acc[mi][ni][1] + b1v;
            float v10 = acc[mi][ni][2] + b0v, v11 = acc[mi][ni][3] + b1v;
            if (epi == EPI_BIAS) {
                *(uint32_t*)&Yb[(size_t)r0*N + c] = pack_bf(v00, v01);
                *(uint32_t*)&Yb[(size_t)r1*N + c] = pack_bf(v10, v11);
            } else if (epi == EPI_GELU) {
                *(float2*)&Yf[(size_t)r0*N + c] = make_float2(gelu_f(v00), gelu_f(v01));
                *(float2*)&Yf[(size_t)r1*N + c] = make_float2(gelu_f(v10), gelu_f(v11));
            } else { // GELU_SUB: fp32 + bf16 dual store
                float2 x0 = *(const float2*)&Xsub[(size_t)r0*N + c];
                float2 x1 = *(const float2*)&Xsub[(size_t)r1*N + c];
                float o00 = x0.x - gelu_f(v00), o01 = x0.y - gelu_f(v01);
                float o10 = x1.x - gelu_f(v10), o11 = x1.y - gelu_f(v11);
                *(float2*)&Yf[(size_t)r0*N + c] = make_float2(o00, o01);
                *(float2*)&Yf[(size_t)r1*N + c] = make_float2(o10, o11);
                *(uint32_t*)&Yb[(size_t)r0*N + c] = pack_bf(o00, o01);
                *(uint32_t*)&Yb[(size_t)r1*N + c] = pack_bf(o10, o11);
            }
        }
    }
}

// ---------------- bf16 tensor-core attention (bf16 I/O), per (bt, head) -----
#define AT_WARPS   7
#define AT_THREADS 224
#define NKP 208
#define KSP2 36
#define VTP2 116
#define PPu  12
#define ATTN_SMEM ((NKP*KSP2 + 64*VTP2 + AT_WARPS*32*PPu) * 4)

__global__ __launch_bounds__(AT_THREADS, 2) void attn_tc(
    const __nv_bfloat16* __restrict__ Qb, const __nv_bfloat16* __restrict__ KVb,
    __nv_bfloat16* __restrict__ Ob)
{
    extern __shared__ uint32_t smu[];
    uint32_t* Ks = smu;                    // [208][36]
    uint32_t* Vt = smu + NKP*KSP2;         // [64][116]
    uint32_t* Ps = Vt + 64*VTP2;           // [7][32][12]
    unsigned short* Vs16 = reinterpret_cast<unsigned short*>(Vt);

    const int bt = blockIdx.x / NHEAD;
    const int h  = blockIdx.x % NHEAD;
    const int tid  = threadIdx.x;
    const int w    = tid >> 5;
    const int lane = tid & 31;
    const int g    = lane >> 2;
    const int qp   = lane & 3;

    // ---- K (u32 direct copy) and V^T (bf16 scatter) from bf16 KV ----
    const uint32_t* kvu = reinterpret_cast<const uint32_t*>(KVb)
                        + (size_t)bt * HWN * 768 + h * 32;
    for (int idx = tid; idx < HWN * 32; idx += AT_THREADS) {
        int r = idx >> 5, j = idx & 31;
        Ks[r*KSP2 + j] = kvu[(size_t)r*768 + j];
        uint32_t v = kvu[(size_t)r*768 + 384 + j];
        int d0 = 2*j;
        Vs16[(d0  )*(VTP2*2) + r] = (unsigned short)(v & 0xffffu);
        Vs16[(d0+1)*(VTP2*2) + r] = (unsigned short)(v >> 16);
    }
    // zero-pad: K rows 196..207, V key-pairs 98..103
    for (int idx = tid; idx < 12*KSP2; idx += AT_THREADS)
        Ks[(196 + idx/KSP2)*KSP2 + idx%KSP2] = 0u;
    for (int idx = tid; idx < 64*6; idx += AT_THREADS)
        Vt[(idx/6)*VTP2 + 98 + idx%6] = 0u;
    __syncthreads();

    // ---- Q fragments (bf16 u32 direct) ----
    uint32_t qa[2][4][4];
    #pragma unroll
    for (int mi = 0; mi < 2; mi++) {
        int r0 = 32*w + 16*mi + g, r1 = r0 + 8;
        const uint32_t* q0 = reinterpret_cast<const uint32_t*>(Qb)
                           + ((size_t)bt*HWN + r0)*384 + h*32;
        const uint32_t* q1 = reinterpret_cast<const uint32_t*>(Qb)
                           + ((size_t)bt*HWN + r1)*384 + h*32;
        bool v0 = (r0 < HWN), v1 = (r1 < HWN);
        #pragma unroll
        for (int kk = 0; kk < 4; kk++) {
            qa[mi][kk][0] = v0 ? q0[8*kk + qp    ] : 0u;
            qa[mi][kk][1] = v1 ? q1[8*kk + qp    ] : 0u;
            qa[mi][kk][2] = v0 ? q0[8*kk + qp + 4] : 0u;
            qa[mi][kk][3] = v1 ? q1[8*kk + qp + 4] : 0u;
        }
    }

    float oacc[2][8][4];
    #pragma unroll
    for (int mi=0; mi<2; mi++)
        #pragma unroll
        for (int di=0; di<8; di++)
            #pragma unroll
            for (int r=0; r<4; r++) oacc[mi][di][r] = 0.f;
    float lp[2][2] = {{0.f,0.f},{0.f,0.f}};
    uint32_t* Pw = Ps + w*32*PPu;

    // ---- main loop: 13 tiles of 16 keys ----
    for (int nt = 0; nt < 13; nt++) {
        const int j0 = nt * 16;
        float c[2][2][4];
        #pragma unroll
        for (int mi=0;mi<2;mi++)
            #pragma unroll
            for (int hf=0;hf<2;hf++)
                #pragma unroll
                for (int r=0;r<4;r++) c[mi][hf][r]=0.f;

        #pragma unroll
        for (int kk = 0; kk < 4; kk++) {
            #pragma unroll
            for (int hf = 0; hf < 2; hf++) {
                const uint32_t* kr = &Ks[(j0 + 8*hf + g)*KSP2];
                uint32_t b0 = kr[8*kk + qp    ];
                uint32_t b1 = kr[8*kk + qp + 4];
                mma_bf16(c[0][hf], qa[0][kk], b0, b1);
                mma_bf16(c[1][hf], qa[1][kk], b0, b1);
            }
        }

        #pragma unroll
        for (int mi = 0; mi < 2; mi++) {
            #pragma unroll
            for (int hf = 0; hf < 2; hf++) {
                const int col0 = j0 + 8*hf + 2*qp;
                const bool m0 = (col0     < HWN);
                const bool m1 = (col0 + 1 < HWN);
                float p00 = m0 ? __expf(fminf(c[mi][hf][0]*SCALE_A, 80.f)) : 0.f;
                float p01 = m1 ? __expf(fminf(c[mi][hf][1]*SCALE_A, 80.f)) : 0.f;
                float p10 = m0 ? __expf(fminf(c[mi][hf][2]*SCALE_A, 80.f)) : 0.f;
                float p11 = m1 ? __expf(fminf(c[mi][hf][3]*SCALE_A, 80.f)) : 0.f;
                lp[mi][0] += p00 + p01;
                lp[mi][1] += p10 + p11;
                Pw[(16*mi   + g)*PPu + 4*hf + qp] = pack_bf(p00, p01);
                Pw[(16*mi+8 + g)*PPu + 4*hf + qp] = pack_bf(p10, p11);
            }
        }
        __syncwarp();

        uint32_t pa[2][4];
        #pragma unroll
        for (int mi = 0; mi < 2; mi++) {
            pa[mi][0] = Pw[(16*mi   + g)*PPu + qp    ];
            pa[mi][1] = Pw[(16*mi+8 + g)*PPu + qp    ];
            pa[mi][2] = Pw[(16*mi   + g)*PPu + qp + 4];
            pa[mi][3] = Pw[(16*mi+8 + g)*PPu + qp + 4];
        }
        __syncwarp();

        const int jp = nt * 8;
        #pragma unroll
        for (int di = 0; di < 8; di++) {
            const uint32_t* vr = &Vt[(8*di + g)*VTP2 + jp];
            uint32_t b0 = vr[qp    ];
            uint32_t b1 = vr[qp + 4];
            mma_bf16(oacc[0][di], pa[0], b0, b1);
            mma_bf16(oacc[1][di], pa[1], b0, b1);
        }
    }

    // ---- finalize ----
    float inv[2][2];
    #pragma unroll
    for (int mi = 0; mi < 2; mi++)
        #pragma unroll
        for (int hf = 0; hf < 2; hf++) {
            float l = lp[mi][hf];
            l += __shfl_xor_sync(0xffffffffu, l, 1);
            l += __shfl_xor_sync(0xffffffffu, l, 2);
            inv[mi][hf] = 1.f / l;
        }

    uint32_t* obu = reinterpret_cast<uint32_t*>(Ob);
    #pragma unroll
    for (int mi = 0; mi < 2; mi++) {
        int r0 = 32*w + 16*mi + g, r1 = r0 + 8;
        float i0 = inv[mi][0], i1 = inv[mi][1];
        #pragma unroll
        for (int di = 0; di < 8; di++) {
            int cu = h*32 + 4*di + qp;   // u32 column
            if (r0 < HWN)
                obu[((size_t)bt*HWN + r0)*384 + cu] =
                    pack_bf(oacc[mi][di][0]*i0, oacc[mi][di][1]*i0);
            if (r1 < HWN)
                obu[((size_t)bt*HWN + r1)*384 + cu] =
                    pack_bf(oacc[mi][di][2]*i1, oacc[mi][di][3]*i1);
        }
    }
}

// ---------------- row mean over C=768 (one warp per row) --------------------
__global__ void rowmean_kernel(const float* __restrict__ X, float* __restrict__ out)
{
    int warp = threadIdx.x >> 5;
    int lane = threadIdx.x & 31;
    int row = blockIdx.x * 8 + warp;
    const float* p = X + (size_t)row * CC;
    float s = 0.f;
    #pragma unroll
    for (int k = 0; k < 6; k++) {
        float4 v = *(const float4*)&p[lane*4 + k*128];
        s += v.x + v.y + v.z + v.w;
    }
    #pragma unroll
    for (int off = 16; off; off >>= 1) s += __shfl_xor_sync(0xffffffffu, s, off);
    if (lane == 0) out[row] = s * (1.0f/768.0f);
}

// ---------------- final: pool_a assembly ------------------------------------
__global__ void final_kernel(const float* __restrict__ mxa, const float* __restrict__ mxd,
                             const float* __restrict__ mg2, float* __restrict__ out)
{
    int i = blockIdx.x * blockDim.x + threadIdx.x;
    if (i < ROWS) out[i] = 0.5f * (mxd[i] - mxa[i]) - mg2[i];
}

// ---------------- launch ----------------------------------------------------
extern "C" void kernel_launch(void* const* d_in, const int* in_sizes, int n_in,
                              void* d_out, int out_size)
{
    const float* x_in  = (const float*)d_in[0];
    const float* Wq_d  = (const float*)d_in[1];
    const float* bq_d  = (const float*)d_in[2];
    const float* Wkv_a = (const float*)d_in[3];
    const float* bkv_a = (const float*)d_in[4];
    const float* Wq_a  = (const float*)d_in[5];
    const float* bq_a  = (const float*)d_in[6];
    const float* Wkv_d = (const float*)d_in[7];
    const float* bkv_d = (const float*)d_in[8];
    const float* Wp_d  = (const float*)d_in[9];
    const float* bp_d  = (const float*)d_in[10];
    const float* Wp_a  = (const float*)d_in[11];
    const float* bp_a  = (const float*)d_in[12];
    float* out = (float*)d_out;

    __nv_bfloat16 *xab, *xdb, *xdnb, *qb, *kvb, *ob;
    float *xd, *xdn, *mxa, *mxd, *mg2;
    uint32_t* wp;
    cudaGetSymbolAddress((void**)&xab,  g_xab);
    cudaGetSymbolAddress((void**)&xdb,  g_xdb);
    cudaGetSymbolAddress((void**)&xdnb, g_xdnb);
    cudaGetSymbolAddress((void**)&qb,   g_qb);
    cudaGetSymbolAddress((void**)&kvb,  g_kvb);
    cudaGetSymbolAddress((void**)&ob,   g_ob);
    cudaGetSymbolAddress((void**)&xd,   g_xd);
    cudaGetSymbolAddress((void**)&xdn,  g_xdn);
    cudaGetSymbolAddress((void**)&wp,   g_wp);
    cudaGetSymbolAddress((void**)&mxa,  g_mxa);
    cudaGetSymbolAddress((void**)&mxd,  g_mxd);
    cudaGetSymbolAddress((void**)&mg2,  g_mg2);

    cudaFuncSetAttribute(attn_tc, cudaFuncAttributeMaxDynamicSharedMemorySize, ATTN_SMEM);
    cudaFuncSetAttribute(gemm_bf, cudaFuncAttributeMaxDynamicSharedMemorySize, GEMM_SMEM);

    // packed-weight offsets (u32 units)
    uint32_t* wp_qd  = wp;                       // 768x768   -> 294912
    uint32_t* wp_kva = wp_qd  + 294912;          // 768x1536  -> 589824
    uint32_t* wp_qa  = wp_kva + 589824;          // 768x768
    uint32_t* wp_kvd = wp_qa  + 294912;          // 768x1536
    uint32_t* wp_pd  = wp_kvd + 589824;          // 768x768
    uint32_t* wp_pa  = wp_pd  + 294912;          // 768x768

    const int g768e  = 384*768,  g1536e = 384*1536;
    packw_kernel<<<(g768e +255)/256, 256>>>(Wq_d,  wp_qd,  384, 768);
    packw_kernel<<<(g1536e+255)/256, 256>>>(Wkv_a, wp_kva, 384, 1536);
    packw_kernel<<<(g768e +255)/256, 256>>>(Wq_a,  wp_qa,  384, 768);
    packw_kernel<<<(g1536e+255)/256, 256>>>(Wkv_d, wp_kvd, 384, 1536);
    packw_kernel<<<(g768e +255)/256, 256>>>(Wp_d,  wp_pd,  384, 768);
    packw_kernel<<<(g768e +255)/256, 256>>>(Wp_a,  wp_pa,  384, 768);

    gather_kernel<<<ROWS, 256>>>(x_in, xab, xdb, xd, mxa, mxd);

    dim3 g768(6, 196), g1536(12, 196);

    // ---- stage d: q from x_d, kv from x_a ----
    gemm_bf<<<g768,  256, GEMM_SMEM>>>(xdb, wp_qd,  bq_d,  qb,  nullptr, nullptr, ROWS, 768,  768, EPI_BIAS);
    gemm_bf<<<g1536, 256, GEMM_SMEM>>>(xab, wp_kva, bkv_a, kvb, nullptr, nullptr, ROWS, 1536, 768, EPI_BIAS);
    attn_tc<<<BT * NHEAD, AT_THREADS, ATTN_SMEM>>>(qb, kvb, ob);
    gemm_bf<<<g768, 256, GEMM_SMEM>>>(ob, wp_pd, bp_d, xdnb, xdn, xd, ROWS, 768, 768, EPI_GELU_SUB);
    rowmean_kernel<<<ROWS/8, 256>>>(xdn, out + ROWS);

    // ---- stage a: q from x_a, kv from x_d_new ----
    gemm_bf<<<g768,  256, GEMM_SMEM>>>(xab,  wp_qa,  bq_a,  qb,  nullptr, nullptr, ROWS, 768,  768, EPI_BIAS);
    gemm_bf<<<g1536, 256, GEMM_SMEM>>>(xdnb, wp_kvd, bkv_d, kvb, nullptr, nullptr, ROWS, 1536, 768, EPI_BIAS);
    attn_tc<<<BT * NHEAD, AT_THREADS, ATTN_SMEM>>>(qb, kvb, ob);
    gemm_bf<<<g768, 256, GEMM_SMEM>>>(ob, wp_pa, bp_a, nullptr, xdn, nullptr, ROWS, 768, 768, EPI_GELU);
    rowmean_kernel<<<ROWS/8, 256>>>(xdn, mg2);

    final_kernel<<<(ROWS + 255)/256, 256>>>(mxa, mxd, mg2, out);
}